// round 3
// baseline (speedup 1.0000x reference)
#include <cuda_runtime.h>
#include <math.h>

#define FULLMASK 0xffffffffu
// B=16, C=384, H=W=64, N=4096, HEADS=4, HD=96

// ---------------- scratch ----------------
__device__ float g_conv[25165824];   // conv out; -> xca proj out; -> x2p (wa proj out)
__device__ float g_pos[1572864];     // [N, C]
__device__ float g_x3[25165824];     // x3 (B,N,C); -> O2 [h][bq][hd][nn]
__device__ float g_ln[25165824];     // LN buffer (reused)
__device__ float g_kv[50331648];     // kv (rows,768), XCA then WA
__device__ float g_O1[25165824];     // XCA attn out; -> wx (unfolded WA input)
__device__ float g_uq[25165824];     // unfold(inp); -> MLP output y
__device__ float g_attn[2359296];    // attention mats (Z x 96 x 96)
__device__ float g_h1[100663296];    // MLP hidden (65536 x 1536)
__device__ float g_norms[24576];     // l2 norms

// ---------------- positional Fourier features ----------------
__global__ void pos_kernel(const float* __restrict__ pw, const float* __restrict__ pb,
                           float* __restrict__ pos)
{
    __shared__ float feat[64];
    int n = blockIdx.x, t = threadIdx.x;
    int hh = n >> 6, ww = n & 63;
    if (t < 64) {
        int j = t, jj = j & 31, m = jj >> 1;
        float v = (j < 32) ? (float)(hh + 1) : (float)(ww + 1);
        v = v / (64.0f + 1e-6f) * 6.283185307179586f;
        float arg = v / powf(10000.0f, (float)m / 16.0f);
        feat[j] = (jj & 1) ? cosf(arg) : sinf(arg);
    }
    __syncthreads();
    float acc = pb[t];
    const float* wr = pw + t * 64;
    #pragma unroll
    for (int j = 0; j < 64; j++) acc += feat[j] * wr[j];
    pos[(long)n * 384 + t] = acc;
}

// ---------------- depthwise 3x3 conv chain step ----------------
__global__ void dwconv_kernel(const float* __restrict__ xin, const float* __restrict__ prevbase,
                              const float* __restrict__ w, const float* __restrict__ bias,
                              float* __restrict__ out, int chunk)
{
    int wq = threadIdx.x;
    int hq = blockIdx.y * blockDim.y + threadIdx.y;
    int bc = blockIdx.z, b = bc / 96, c = bc % 96;
    const float* p1 = xin + ((long)b * 384 + chunk * 96 + c) * 4096;
    const float* p0 = (chunk > 0) ? prevbase + ((long)b * 384 + (chunk - 1) * 96 + c) * 4096 : nullptr;
    const float* wp = w + (chunk * 96 + c) * 9;
    float acc = bias[chunk * 96 + c];
    #pragma unroll
    for (int dy = 0; dy < 3; dy++) {
        int y = hq + dy - 1;
        if (y < 0 || y >= 64) continue;
        #pragma unroll
        for (int dx = 0; dx < 3; dx++) {
            int xx = wq + dx - 1;
            if (xx < 0 || xx >= 64) continue;
            float v = p1[y * 64 + xx];
            if (p0) v += p0[y * 64 + xx];
            acc += v * wp[dy * 3 + dx];
        }
    }
    out[((long)b * 384 + chunk * 96 + c) * 4096 + hq * 64 + wq] = acc;
}

// ---------------- transpose (B,C,N)->(B,N,C) + pos (c>=288 from raw input) ----------------
__global__ void t1_kernel(const float* __restrict__ conv, const float* __restrict__ xin,
                          const float* __restrict__ pos, float* __restrict__ x3)
{
    __shared__ float tile[32][33];
    int n0 = blockIdx.x << 5, c0 = blockIdx.y << 5, b = blockIdx.z;
    int tx = threadIdx.x, ty = threadIdx.y;
    const float* src = (c0 >= 288) ? xin : conv;
    #pragma unroll
    for (int r = 0; r < 4; r++)
        tile[ty + r * 8][tx] = src[((long)b * 384 + c0 + ty + r * 8) * 4096 + n0 + tx];
    __syncthreads();
    #pragma unroll
    for (int r = 0; r < 4; r++) {
        int n = n0 + ty + r * 8, c = c0 + tx;
        x3[((long)b * 4096 + n) * 384 + c] = tile[tx][ty + r * 8] + pos[(long)n * 384 + c];
    }
}

// ---------------- unfold(inp) -> uq [(b*4+q), p, c] ----------------
__global__ void t2_kernel(const float* __restrict__ xin, float* __restrict__ uq)
{
    __shared__ float tile[32][33];
    int n0 = blockIdx.x << 5, c0 = blockIdx.y << 5, b = blockIdx.z;
    int tx = threadIdx.x, ty = threadIdx.y;
    #pragma unroll
    for (int r = 0; r < 4; r++)
        tile[ty + r * 8][tx] = xin[((long)b * 384 + c0 + ty + r * 8) * 4096 + n0 + tx];
    __syncthreads();
    #pragma unroll
    for (int r = 0; r < 4; r++) {
        int n = n0 + ty + r * 8, c = c0 + tx;
        int hh = n >> 6, ww = n & 63;
        int q = ((hh & 1) << 1) | (ww & 1);
        int p = ((hh >> 1) << 5) | (ww >> 1);
        uq[((long)(b * 4 + q) * 1024 + p) * 384 + c] = tile[tx][ty + r * 8];
    }
}

// ---------------- LayerNorm over C=384; gather=1 applies fold() mapping on input ----------------
__global__ void ln_kernel(const float* __restrict__ in, const float* __restrict__ w,
                          const float* __restrict__ bvec, float* __restrict__ out, int gather)
{
    int row = blockIdx.x, t = threadIdx.x;
    long ibase;
    if (gather) {
        int b = row >> 12, n = row & 4095;
        int hh = n >> 6, ww = n & 63;
        int q = ((hh & 1) << 1) | (ww & 1);
        int p = ((hh >> 1) << 5) | (ww >> 1);
        ibase = ((long)(b * 4 + q) * 1024 + p) * 384;
    } else ibase = (long)row * 384;
    float v0 = in[ibase + t], v1 = in[ibase + t + 128], v2 = in[ibase + t + 256];
    float s = v0 + v1 + v2;
    float q2 = v0 * v0 + v1 * v1 + v2 * v2;
    #pragma unroll
    for (int o = 16; o; o >>= 1) {
        s += __shfl_down_sync(FULLMASK, s, o);
        q2 += __shfl_down_sync(FULLMASK, q2, o);
    }
    __shared__ float ss[4], sq[4], smean, srstd;
    int wid = t >> 5, lane = t & 31;
    if (lane == 0) { ss[wid] = s; sq[wid] = q2; }
    __syncthreads();
    if (t == 0) {
        float S = ss[0] + ss[1] + ss[2] + ss[3];
        float Q = sq[0] + sq[1] + sq[2] + sq[3];
        float m = S * (1.0f / 384.0f);
        smean = m;
        srstd = rsqrtf(Q * (1.0f / 384.0f) - m * m + 1e-6f);
    }
    __syncthreads();
    float m = smean, r = srstd;
    long ob = (long)row * 384;
    out[ob + t]       = (v0 - m) * r * w[t]       + bvec[t];
    out[ob + t + 128] = (v1 - m) * r * w[t + 128] + bvec[t + 128];
    out[ob + t + 256] = (v2 - m) * r * w[t + 256] + bvec[t + 256];
}

// ---------------- per-(batch, channel) L2 norm of k-part columns ----------------
__global__ void norms_kernel(const float* __restrict__ kv, float* __restrict__ norms, int R)
{
    int b = blockIdx.x, t = threadIdx.x;
    const float* p = kv + (long)b * R * 768 + t;
    float s = 0.f;
    for (int n = 0; n < R; n++) { float v = p[(long)n * 768]; s += v * v; }
    norms[b * 384 + t] = sqrtf(s);
}

// ---------------- XCA softmax over d, with temp[h]/norm_d scaling ----------------
__global__ void xca_softmax_k(float* __restrict__ G, const float* __restrict__ norms,
                              const float* __restrict__ temp)
{
    int warp = threadIdx.x >> 5, lane = threadIdx.x & 31;
    int row = blockIdx.x * 8 + warp;
    int bh = row / 96, b = bh >> 2, h = bh & 3;
    float tv = temp[h];
    float* g = G + (long)row * 96;
    const float* nb = norms + b * 384 + h * 96;
    float v[3];
    #pragma unroll
    for (int i = 0; i < 3; i++) { int d = lane + i * 32; v[i] = g[d] * tv / fmaxf(nb[d], 1e-12f); }
    float m = fmaxf(v[0], fmaxf(v[1], v[2]));
    #pragma unroll
    for (int o = 16; o; o >>= 1) m = fmaxf(m, __shfl_xor_sync(FULLMASK, m, o));
    float e[3], s = 0.f;
    #pragma unroll
    for (int i = 0; i < 3; i++) { e[i] = expf(v[i] - m); s += e[i]; }
    #pragma unroll
    for (int o = 16; o; o >>= 1) s += __shfl_xor_sync(FULLMASK, s, o);
    float inv = 1.0f / s;
    #pragma unroll
    for (int i = 0; i < 3; i++) g[lane + i * 32] = e[i] * inv;
}

// ---------------- WA double softmax: a = 0.5*l/sqrt(96) + 0.5*softmax(l); softmax(a) ----------------
__global__ void wa_softmax_k(float* __restrict__ G, const float* __restrict__ norms)
{
    int warp = threadIdx.x >> 5, lane = threadIdx.x & 31;
    int row = blockIdx.x * 8 + warp;
    int bh = row / 96, bq = bh >> 2, h = bh & 3;
    float* g = G + (long)row * 96;
    const float* nb = norms + bq * 384 + h * 96;
    float l[3];
    #pragma unroll
    for (int i = 0; i < 3; i++) { int d = lane + i * 32; l[i] = g[d] / fmaxf(nb[d], 1e-12f); }
    float m1 = fmaxf(l[0], fmaxf(l[1], l[2]));
    #pragma unroll
    for (int o = 16; o; o >>= 1) m1 = fmaxf(m1, __shfl_xor_sync(FULLMASK, m1, o));
    float e[3], s1 = 0.f;
    #pragma unroll
    for (int i = 0; i < 3; i++) { e[i] = expf(l[i] - m1); s1 += e[i]; }
    #pragma unroll
    for (int o = 16; o; o >>= 1) s1 += __shfl_xor_sync(FULLMASK, s1, o);
    float inv1 = 1.0f / s1, a[3];
    #pragma unroll
    for (int i = 0; i < 3; i++) a[i] = l[i] * 0.051031036307982884f + 0.5f * e[i] * inv1;
    float m2 = fmaxf(a[0], fmaxf(a[1], a[2]));
    #pragma unroll
    for (int o = 16; o; o >>= 1) m2 = fmaxf(m2, __shfl_xor_sync(FULLMASK, m2, o));
    float e2[3], s2 = 0.f;
    #pragma unroll
    for (int i = 0; i < 3; i++) { e2[i] = expf(a[i] - m2); s2 += e2[i]; }
    #pragma unroll
    for (int o = 16; o; o >>= 1) s2 += __shfl_xor_sync(FULLMASK, s2, o);
    float inv2 = 1.0f / s2;
    #pragma unroll
    for (int i = 0; i < 3; i++) g[lane + i * 32] = e2[i] * inv2;
}

// ---------------- x4 = x3 + gxca*xca; conv_out scale; unfold scatter ----------------
__global__ void e1_kernel(const float* __restrict__ x3, const float* __restrict__ xca,
                          const float* __restrict__ gx, const float* __restrict__ cw,
                          const float* __restrict__ cb, float* __restrict__ wx)
{
    long idx = (long)blockIdx.x * blockDim.x + threadIdx.x;
    if (idx >= 25165824L) return;
    int c = (int)(idx % 384);
    long rn = idx / 384;
    int n = (int)(rn & 4095), b = (int)(rn >> 12);
    float v = (x3[idx] + gx[c] * xca[idx]) * cw[c] + cb[c];
    int hh = n >> 6, ww = n & 63;
    int q = ((hh & 1) << 1) | (ww & 1);
    int p = ((hh >> 1) << 5) | (ww >> 1);
    wx[((long)(b * 4 + q) * 1024 + p) * 384 + c] = v;
}

// ---------------- final: out[b,c,n] = inp + gamma[c]*y[b,n,c] ----------------
__global__ void final_kernel(const float* __restrict__ y, const float* __restrict__ xin,
                             const float* __restrict__ gamma, float* __restrict__ out)
{
    __shared__ float tile[32][33];
    int n0 = blockIdx.x << 5, c0 = blockIdx.y << 5, b = blockIdx.z;
    int tx = threadIdx.x, ty = threadIdx.y;
    #pragma unroll
    for (int r = 0; r < 4; r++)
        tile[ty + r * 8][tx] = y[((long)b * 4096 + n0 + ty + r * 8) * 384 + c0 + tx];
    __syncthreads();
    #pragma unroll
    for (int r = 0; r < 4; r++) {
        int c = c0 + ty + r * 8;
        long o = ((long)b * 384 + c) * 4096 + n0 + tx;
        out[o] = xin[o] + gamma[c] * tile[tx][ty + r * 8];
    }
}

// ---------------- generic tiled SGEMM (64x64x32, 4x4 microtile, batched) ----------------
// OPA: 0 -> a(i,k)=A[i*lda+k], 1 -> a(i,k)=A[k*lda+i]
// OPB: 0 -> b(k,j)=B[k*ldb+j], 1 -> b(k,j)=B[j*ldb+k].  EPI=1: exact GELU after bias.
template<int OPA, int OPB, int EPI>
__global__ void __launch_bounds__(256) gemm_k(
    const float* __restrict__ Ag, const float* __restrict__ Bg,
    const float* __restrict__ bias, float* __restrict__ Cg,
    int M, int N, int K, int lda, int ldb, int ldc,
    long sA1, long sA2, long sB1, long sB2, long sC1, long sC2, int HB)
{
    int z = blockIdx.z, zo = z / HB, zi = z - zo * HB;
    const float* A = Ag + zo * sA1 + zi * sA2;
    const float* Bm = Bg + zo * sB1 + zi * sB2;
    float* C = Cg + zo * sC1 + zi * sC2;

    __shared__ __align__(16) float As[32][68];
    __shared__ __align__(16) float Bs[32][68];

    int tid = threadIdx.x;
    int tx = tid & 15, ty = tid >> 4;
    int m0 = blockIdx.x * 64, n0 = blockIdx.y * 64;

    float acc[4][4];
    #pragma unroll
    for (int i = 0; i < 4; i++)
        #pragma unroll
        for (int j = 0; j < 4; j++) acc[i][j] = 0.f;

    for (int k0 = 0; k0 < K; k0 += 32) {
        if (OPA == 0) {
            int k = tid & 31, i = tid >> 5;
            #pragma unroll
            for (int r = 0; r < 8; r++) {
                int ii = i + r * 8;
                As[k][ii] = (m0 + ii < M) ? A[(long)(m0 + ii) * lda + k0 + k] : 0.f;
            }
        } else {
            int i = tid & 63, kk = tid >> 6;
            #pragma unroll
            for (int r = 0; r < 8; r++) {
                int k = kk + r * 4;
                As[k][i] = (m0 + i < M) ? A[(long)(k0 + k) * lda + m0 + i] : 0.f;
            }
        }
        if (OPB == 0) {
            int j = tid & 63, kk = tid >> 6;
            #pragma unroll
            for (int r = 0; r < 8; r++) {
                int k = kk + r * 4;
                Bs[k][j] = (n0 + j < N) ? Bm[(long)(k0 + k) * ldb + n0 + j] : 0.f;
            }
        } else {
            int k = tid & 31, j = tid >> 5;
            #pragma unroll
            for (int r = 0; r < 8; r++) {
                int jj = j + r * 8;
                Bs[k][jj] = (n0 + jj < N) ? Bm[(long)(n0 + jj) * ldb + k0 + k] : 0.f;
            }
        }
        __syncthreads();
        #pragma unroll
        for (int k = 0; k < 32; k++) {
            float4 av = *(const float4*)&As[k][ty * 4];
            float4 bv = *(const float4*)&Bs[k][tx * 4];
            float a4[4] = {av.x, av.y, av.z, av.w};
            float b4[4] = {bv.x, bv.y, bv.z, bv.w};
            #pragma unroll
            for (int i = 0; i < 4; i++)
                #pragma unroll
                for (int j = 0; j < 4; j++)
                    acc[i][j] += a4[i] * b4[j];
        }
        __syncthreads();
    }
    #pragma unroll
    for (int i = 0; i < 4; i++) {
        int mi = m0 + ty * 4 + i;
        if (mi >= M) continue;
        #pragma unroll
        for (int j = 0; j < 4; j++) {
            int nj = n0 + tx * 4 + j;
            if (nj >= N) continue;
            float v = acc[i][j];
            if (bias) v += bias[nj];
            if (EPI == 1) v = 0.5f * v * (1.0f + erff(v * 0.7071067811865476f));
            C[(long)mi * ldc + nj] = v;
        }
    }
}

template<int OPA, int OPB, int EPI>
static void lg(const float* A, const float* B, const float* bias, float* C,
               int M, int N, int K, int lda, int ldb, int ldc,
               long sA1, long sA2, long sB1, long sB2, long sC1, long sC2, int HB, int Z)
{
    dim3 grid((M + 63) / 64, (N + 63) / 64, Z);
    gemm_k<OPA, OPB, EPI><<<grid, 256>>>(A, B, bias, C, M, N, K, lda, ldb, ldc,
                                         sA1, sA2, sB1, sB2, sC1, sC2, HB);
}

extern "C" void kernel_launch(void* const* d_in, const int* in_sizes, int n_in,
                              void* d_out, int out_size)
{
    const float* x          = (const float*)d_in[0];
    const float* convs_w    = (const float*)d_in[1];
    const float* convs_b    = (const float*)d_in[2];
    const float* pos_w      = (const float*)d_in[3];
    const float* pos_b      = (const float*)d_in[4];
    const float* ln_xca_w   = (const float*)d_in[5];
    const float* ln_xca_b   = (const float*)d_in[6];
    const float* gamma_xca  = (const float*)d_in[7];
    const float* xca_temp   = (const float*)d_in[8];
    const float* xca_kv_w   = (const float*)d_in[9];
    const float* xca_kv_b   = (const float*)d_in[10];
    const float* xca_proj_w = (const float*)d_in[11];
    const float* xca_proj_b = (const float*)d_in[12];
    const float* conv_out_w = (const float*)d_in[13];
    const float* conv_out_b = (const float*)d_in[14];
    const float* wa_kv_w    = (const float*)d_in[15];
    const float* wa_kv_b    = (const float*)d_in[16];
    const float* wa_proj_w  = (const float*)d_in[17];
    const float* wa_proj_b  = (const float*)d_in[18];
    const float* ln_w       = (const float*)d_in[19];
    const float* ln_b       = (const float*)d_in[20];
    const float* pw1_w      = (const float*)d_in[21];
    const float* pw1_b      = (const float*)d_in[22];
    const float* pw2_w      = (const float*)d_in[23];
    const float* pw2_b      = (const float*)d_in[24];
    const float* gamma      = (const float*)d_in[25];
    float* out = (float*)d_out;

    float *conv, *pos, *x3, *ln, *kv, *O1, *uq, *attn, *h1, *norms;
    cudaGetSymbolAddress((void**)&conv,  g_conv);
    cudaGetSymbolAddress((void**)&pos,   g_pos);
    cudaGetSymbolAddress((void**)&x3,    g_x3);
    cudaGetSymbolAddress((void**)&ln,    g_ln);
    cudaGetSymbolAddress((void**)&kv,    g_kv);
    cudaGetSymbolAddress((void**)&O1,    g_O1);
    cudaGetSymbolAddress((void**)&uq,    g_uq);
    cudaGetSymbolAddress((void**)&attn,  g_attn);
    cudaGetSymbolAddress((void**)&h1,    g_h1);
    cudaGetSymbolAddress((void**)&norms, g_norms);

    // 1. positional features
    pos_kernel<<<4096, 384>>>(pos_w, pos_b, pos);

    // 2. Res2Net depthwise conv chain (channels 0..287; 288..383 pass through)
    dim3 cg(1, 16, 16 * 96), cb(64, 4);
    dwconv_kernel<<<cg, cb>>>(x, conv, convs_w, convs_b, conv, 0);
    dwconv_kernel<<<cg, cb>>>(x, conv, convs_w, convs_b, conv, 1);
    dwconv_kernel<<<cg, cb>>>(x, conv, convs_w, convs_b, conv, 2);

    // 3. x3 = transpose + pos;  uq = unfold(inp)
    dim3 tg(128, 12, 16), tb(32, 8);
    t1_kernel<<<tg, tb>>>(conv, x, pos, x3);
    t2_kernel<<<tg, tb>>>(x, uq);

    // 4. XCA: LN, kv, norms, logits, softmax, AV, proj
    ln_kernel<<<65536, 128>>>(x3, ln_xca_w, ln_xca_b, ln, 0);
    lg<0,1,0>(ln, xca_kv_w, xca_kv_b, kv, 65536, 768, 384, 384, 384, 768,
              0, 0, 0, 0, 0, 0, 1, 1);
    norms_kernel<<<16, 384>>>(kv, norms, 4096);
    lg<0,0,0>(x, kv, nullptr, attn, 96, 96, 4096, 4096, 768, 96,
              (long)384*4096, (long)96*4096, (long)4096*768, 96,
              (long)4*9216, 9216, 4, 64);
    xca_softmax_k<<<768, 256>>>(attn, norms, xca_temp);
    lg<0,1,0>(kv + 384, attn, nullptr, O1, 4096, 96, 96, 768, 96, 384,
              (long)4096*768, 96, (long)4*9216, 9216, (long)4096*384, 96, 4, 64);
    lg<0,1,0>(O1, xca_proj_w, xca_proj_b, conv, 65536, 384, 384, 384, 384, 384,
              0, 0, 0, 0, 0, 0, 1, 1);

    // 5. residual + conv_out scale + unfold -> wx (reuses O1)
    e1_kernel<<<(25165824 + 255) / 256, 256>>>(x3, conv, gamma_xca, conv_out_w, conv_out_b, O1);

    // 6. Window attention
    lg<0,1,0>(O1, wa_kv_w, wa_kv_b, kv, 65536, 768, 384, 384, 384, 768,
              0, 0, 0, 0, 0, 0, 1, 1);
    norms_kernel<<<64, 384>>>(kv, norms, 1024);
    lg<1,0,0>(uq, kv, nullptr, attn, 96, 96, 1024, 384, 768, 96,
              (long)1024*384, 96, (long)1024*768, 96, (long)4*9216, 9216, 4, 256);
    wa_softmax_k<<<3072, 256>>>(attn, norms);
    // AV written directly in scrambled layout [h][bq][hd][nn] (reuses x3)
    lg<0,1,0>(attn, kv + 384, nullptr, x3, 96, 1024, 96, 96, 768, 1024,
              (long)4*9216, 9216, (long)1024*768, 96,
              (long)96*1024, (long)64*96*1024, 4, 256);
    lg<0,1,0>(x3, wa_proj_w, wa_proj_b, conv, 65536, 384, 384, 384, 384, 384,
              0, 0, 0, 0, 0, 0, 1, 1);

    // 7. fold + LN (gather), MLP with exact GELU, final residual
    ln_kernel<<<65536, 128>>>(conv, ln_w, ln_b, ln, 1);
    lg<0,1,1>(ln, pw1_w, pw1_b, h1, 65536, 1536, 384, 384, 384, 1536,
              0, 0, 0, 0, 0, 0, 1, 1);
    lg<0,1,0>(h1, pw2_w, pw2_b, uq, 65536, 384, 1536, 1536, 1536, 384,
              0, 0, 0, 0, 0, 0, 1, 1);
    final_kernel<<<tg, tb>>>(uq, x, gamma, out);
}

// round 4
// speedup vs baseline: 4.3121x; 4.3121x over previous
#include <cuda_runtime.h>
#include <cuda_bf16.h>
#include <math.h>

#define FULLMASK 0xffffffffu
typedef __nv_bfloat16 bf16;
// B=16, C=384, H=W=64, N=4096, HEADS=4, HD=96

// ---------------- scratch ----------------
__device__ float g_conv[25165824];   // dwconv out -> xca proj out -> wa proj out
__device__ float g_pos[1572864];     // [N, C]
__device__ float g_x3[25165824];     // x3 fp32; later reused (as bf16) for WA AV out
__device__ float g_attn[2359296];    // fp32 logits (Z x 96 x 96)
__device__ float g_y[25165824];      // MLP out fp32
__device__ float g_norms[24576];
__device__ bf16 g_bx[25165824];      // bf16(x)
__device__ bf16 g_lnb[25165824];     // LN out bf16 (XCA then final LN)
__device__ bf16 g_kv[50331648];      // kv bf16 (XCA then WA)
__device__ bf16 g_kt[25165824];      // kT bf16 (XCA then WA)
__device__ bf16 g_b1[25165824];      // XCA AV out -> wx (WA input)
__device__ bf16 g_uqt[25165824];     // unfold(inp) in [bq][c][p] layout
__device__ bf16 g_battn[2359296];    // softmax probs bf16
__device__ bf16 g_h1[100663296];     // MLP hidden bf16
__device__ bf16 g_wt[2064384];       // converted weights

// ---------------- fp32 -> bf16 convert ----------------
__global__ void cvt_kernel(const float* __restrict__ in, bf16* __restrict__ out, long n)
{
    long i = (long)blockIdx.x * 256 + threadIdx.x;
    if (i < n) out[i] = __float2bfloat16(in[i]);
}

// ---------------- positional Fourier features ----------------
__global__ void pos_kernel(const float* __restrict__ pw, const float* __restrict__ pb,
                           float* __restrict__ pos)
{
    __shared__ float feat[64];
    int n = blockIdx.x, t = threadIdx.x;
    int hh = n >> 6, ww = n & 63;
    if (t < 64) {
        int j = t, jj = j & 31, m = jj >> 1;
        float v = (j < 32) ? (float)(hh + 1) : (float)(ww + 1);
        v = v / (64.0f + 1e-6f) * 6.283185307179586f;
        float arg = v / powf(10000.0f, (float)m / 16.0f);
        feat[j] = (jj & 1) ? cosf(arg) : sinf(arg);
    }
    __syncthreads();
    float acc = pb[t];
    const float* wr = pw + t * 64;
    #pragma unroll
    for (int j = 0; j < 64; j++) acc += feat[j] * wr[j];
    pos[(long)n * 384 + t] = acc;
}

// ---------------- depthwise 3x3 conv chain step ----------------
__global__ void dwconv_kernel(const float* __restrict__ xin, const float* __restrict__ prevbase,
                              const float* __restrict__ w, const float* __restrict__ bias,
                              float* __restrict__ out, int chunk)
{
    int wq = threadIdx.x;
    int hq = blockIdx.y * blockDim.y + threadIdx.y;
    int bc = blockIdx.z, b = bc / 96, c = bc % 96;
    const float* p1 = xin + ((long)b * 384 + chunk * 96 + c) * 4096;
    const float* p0 = (chunk > 0) ? prevbase + ((long)b * 384 + (chunk - 1) * 96 + c) * 4096 : nullptr;
    const float* wp = w + (chunk * 96 + c) * 9;
    float acc = bias[chunk * 96 + c];
    #pragma unroll
    for (int dy = 0; dy < 3; dy++) {
        int y = hq + dy - 1;
        if (y < 0 || y >= 64) continue;
        #pragma unroll
        for (int dx = 0; dx < 3; dx++) {
            int xx = wq + dx - 1;
            if (xx < 0 || xx >= 64) continue;
            float v = p1[y * 64 + xx];
            if (p0) v += p0[y * 64 + xx];
            acc += v * wp[dy * 3 + dx];
        }
    }
    out[((long)b * 384 + chunk * 96 + c) * 4096 + hq * 64 + wq] = acc;
}

// ---------------- transpose (B,C,N)->(B,N,C) + pos ----------------
__global__ void t1_kernel(const float* __restrict__ conv, const float* __restrict__ xin,
                          const float* __restrict__ pos, float* __restrict__ x3)
{
    __shared__ float tile[32][33];
    int n0 = blockIdx.x << 5, c0 = blockIdx.y << 5, b = blockIdx.z;
    int tx = threadIdx.x, ty = threadIdx.y;
    const float* src = (c0 >= 288) ? xin : conv;
    #pragma unroll
    for (int r = 0; r < 4; r++)
        tile[ty + r * 8][tx] = src[((long)b * 384 + c0 + ty + r * 8) * 4096 + n0 + tx];
    __syncthreads();
    #pragma unroll
    for (int r = 0; r < 4; r++) {
        int n = n0 + ty + r * 8, c = c0 + tx;
        x3[((long)b * 4096 + n) * 384 + c] = tile[tx][ty + r * 8] + pos[(long)n * 384 + c];
    }
}

// ---------------- unfold(inp) directly in [bq][c][p] layout, bf16 ----------------
__global__ void uqt_kernel(const float* __restrict__ x, bf16* __restrict__ uqT)
{
    long idx = (long)blockIdx.x * 256 + threadIdx.x;
    if (idx >= 25165824L) return;
    int p = (int)(idx & 1023);
    long r = idx >> 10;
    int c = (int)(r % 384);
    int bq = (int)(r / 384);
    int q = bq & 3, b = bq >> 2;
    int hh = ((p >> 5) << 1) | (q >> 1);
    int ww = ((p & 31) << 1) | (q & 1);
    uqT[idx] = __float2bfloat16(x[((long)b * 384 + c) * 4096 + hh * 64 + ww]);
}

// ---------------- kv k-part transpose: kv[bz][n][768](cols 0..383) -> kT[bz][d][R] ----------------
__global__ void tk_kernel(const bf16* __restrict__ kv, bf16* __restrict__ kT, int R)
{
    __shared__ bf16 tile[32][33];
    int n0 = blockIdx.x << 5, d0 = blockIdx.y << 5, bz = blockIdx.z;
    int tx = threadIdx.x, ty = threadIdx.y;
    #pragma unroll
    for (int r = 0; r < 4; r++)
        tile[ty + r * 8][tx] = kv[((long)bz * R + n0 + ty + r * 8) * 768 + d0 + tx];
    __syncthreads();
    #pragma unroll
    for (int r = 0; r < 4; r++)
        kT[((long)bz * 384 + d0 + ty + r * 8) * R + n0 + tx] = tile[tx][ty + r * 8];
}

// ---------------- L2 norms from kT (warp per (bz,d) column) ----------------
__global__ void norms2_k(const bf16* __restrict__ kT, float* __restrict__ norms, int R)
{
    int gw = blockIdx.x * 8 + (threadIdx.x >> 5);
    int lane = threadIdx.x & 31;
    const bf16* p = kT + (long)gw * R;
    float s = 0.f;
    for (int i = lane * 2; i < R; i += 64) {
        __nv_bfloat162 v = *(const __nv_bfloat162*)(p + i);
        float a = __bfloat162float(v.x), b = __bfloat162float(v.y);
        s += a * a + b * b;
    }
    #pragma unroll
    for (int o = 16; o; o >>= 1) s += __shfl_xor_sync(FULLMASK, s, o);
    if (lane == 0) norms[gw] = sqrtf(s);
}

// ---------------- LayerNorm over C=384; gather=1 applies fold() mapping; bf16 out ----------------
__global__ void ln_kernel(const float* __restrict__ in, const float* __restrict__ w,
                          const float* __restrict__ bvec, bf16* __restrict__ out, int gather)
{
    int row = blockIdx.x, t = threadIdx.x;
    long ibase;
    if (gather) {
        int b = row >> 12, n = row & 4095;
        int hh = n >> 6, ww = n & 63;
        int q = ((hh & 1) << 1) | (ww & 1);
        int p = ((hh >> 1) << 5) | (ww >> 1);
        ibase = ((long)(b * 4 + q) * 1024 + p) * 384;
    } else ibase = (long)row * 384;
    float v0 = in[ibase + t], v1 = in[ibase + t + 128], v2 = in[ibase + t + 256];
    float s = v0 + v1 + v2;
    float q2 = v0 * v0 + v1 * v1 + v2 * v2;
    #pragma unroll
    for (int o = 16; o; o >>= 1) {
        s += __shfl_down_sync(FULLMASK, s, o);
        q2 += __shfl_down_sync(FULLMASK, q2, o);
    }
    __shared__ float ss[4], sq[4], smean, srstd;
    int wid = t >> 5, lane = t & 31;
    if (lane == 0) { ss[wid] = s; sq[wid] = q2; }
    __syncthreads();
    if (t == 0) {
        float S = ss[0] + ss[1] + ss[2] + ss[3];
        float Q = sq[0] + sq[1] + sq[2] + sq[3];
        float m = S * (1.0f / 384.0f);
        smean = m;
        srstd = rsqrtf(Q * (1.0f / 384.0f) - m * m + 1e-6f);
    }
    __syncthreads();
    float m = smean, r = srstd;
    long ob = (long)row * 384;
    out[ob + t]       = __float2bfloat16((v0 - m) * r * w[t]       + bvec[t]);
    out[ob + t + 128] = __float2bfloat16((v1 - m) * r * w[t + 128] + bvec[t + 128]);
    out[ob + t + 256] = __float2bfloat16((v2 - m) * r * w[t + 256] + bvec[t + 256]);
}

// ---------------- XCA softmax over d, temp[h]/norm_d scaling; bf16 probs out ----------------
__global__ void xca_softmax_k(const float* __restrict__ G, const float* __restrict__ norms,
                              const float* __restrict__ temp, bf16* __restrict__ P)
{
    int warp = threadIdx.x >> 5, lane = threadIdx.x & 31;
    int row = blockIdx.x * 8 + warp;
    int bh = row / 96, b = bh >> 2, h = bh & 3;
    float tv = temp[h];
    const float* g = G + (long)row * 96;
    bf16* o = P + (long)row * 96;
    const float* nb = norms + b * 384 + h * 96;
    float v[3];
    #pragma unroll
    for (int i = 0; i < 3; i++) { int d = lane + i * 32; v[i] = g[d] * tv / fmaxf(nb[d], 1e-12f); }
    float m = fmaxf(v[0], fmaxf(v[1], v[2]));
    #pragma unroll
    for (int o2 = 16; o2; o2 >>= 1) m = fmaxf(m, __shfl_xor_sync(FULLMASK, m, o2));
    float e[3], s = 0.f;
    #pragma unroll
    for (int i = 0; i < 3; i++) { e[i] = expf(v[i] - m); s += e[i]; }
    #pragma unroll
    for (int o2 = 16; o2; o2 >>= 1) s += __shfl_xor_sync(FULLMASK, s, o2);
    float inv = 1.0f / s;
    #pragma unroll
    for (int i = 0; i < 3; i++) o[lane + i * 32] = __float2bfloat16(e[i] * inv);
}

// ---------------- WA double softmax; bf16 probs out ----------------
__global__ void wa_softmax_k(const float* __restrict__ G, const float* __restrict__ norms,
                             bf16* __restrict__ P)
{
    int warp = threadIdx.x >> 5, lane = threadIdx.x & 31;
    int row = blockIdx.x * 8 + warp;
    int bh = row / 96, bq = bh >> 2, h = bh & 3;
    const float* g = G + (long)row * 96;
    bf16* o = P + (long)row * 96;
    const float* nb = norms + bq * 384 + h * 96;
    float l[3];
    #pragma unroll
    for (int i = 0; i < 3; i++) { int d = lane + i * 32; l[i] = g[d] / fmaxf(nb[d], 1e-12f); }
    float m1 = fmaxf(l[0], fmaxf(l[1], l[2]));
    #pragma unroll
    for (int o2 = 16; o2; o2 >>= 1) m1 = fmaxf(m1, __shfl_xor_sync(FULLMASK, m1, o2));
    float e[3], s1 = 0.f;
    #pragma unroll
    for (int i = 0; i < 3; i++) { e[i] = expf(l[i] - m1); s1 += e[i]; }
    #pragma unroll
    for (int o2 = 16; o2; o2 >>= 1) s1 += __shfl_xor_sync(FULLMASK, s1, o2);
    float inv1 = 1.0f / s1, a[3];
    #pragma unroll
    for (int i = 0; i < 3; i++) a[i] = l[i] * 0.051031036307982884f + 0.5f * e[i] * inv1;
    float m2 = fmaxf(a[0], fmaxf(a[1], a[2]));
    #pragma unroll
    for (int o2 = 16; o2; o2 >>= 1) m2 = fmaxf(m2, __shfl_xor_sync(FULLMASK, m2, o2));
    float e2[3], s2 = 0.f;
    #pragma unroll
    for (int i = 0; i < 3; i++) { e2[i] = expf(a[i] - m2); s2 += e2[i]; }
    #pragma unroll
    for (int o2 = 16; o2; o2 >>= 1) s2 += __shfl_xor_sync(FULLMASK, s2, o2);
    float inv2 = 1.0f / s2;
    #pragma unroll
    for (int i = 0; i < 3; i++) o[lane + i * 32] = __float2bfloat16(e2[i] * inv2);
}

// ---------------- x4=x3+gxca*xca; conv_out scale; unfold scatter; bf16 out ----------------
__global__ void e1_kernel(const float* __restrict__ x3, const float* __restrict__ xca,
                          const float* __restrict__ gx, const float* __restrict__ cw,
                          const float* __restrict__ cb, bf16* __restrict__ wx)
{
    long idx = (long)blockIdx.x * blockDim.x + threadIdx.x;
    if (idx >= 25165824L) return;
    int c = (int)(idx % 384);
    long rn = idx / 384;
    int n = (int)(rn & 4095), b = (int)(rn >> 12);
    float v = (x3[idx] + gx[c] * xca[idx]) * cw[c] + cb[c];
    int hh = n >> 6, ww = n & 63;
    int q = ((hh & 1) << 1) | (ww & 1);
    int p = ((hh >> 1) << 5) | (ww >> 1);
    wx[((long)(b * 4 + q) * 1024 + p) * 384 + c] = __float2bfloat16(v);
}

// ---------------- final: out[b,c,n] = inp + gamma[c]*y[b,n,c] ----------------
__global__ void final_kernel(const float* __restrict__ y, const float* __restrict__ xin,
                             const float* __restrict__ gamma, float* __restrict__ out)
{
    __shared__ float tile[32][33];
    int n0 = blockIdx.x << 5, c0 = blockIdx.y << 5, b = blockIdx.z;
    int tx = threadIdx.x, ty = threadIdx.y;
    #pragma unroll
    for (int r = 0; r < 4; r++)
        tile[ty + r * 8][tx] = y[((long)b * 4096 + n0 + ty + r * 8) * 384 + c0 + tx];
    __syncthreads();
    #pragma unroll
    for (int r = 0; r < 4; r++) {
        int c = c0 + ty + r * 8;
        long o = ((long)b * 384 + c) * 4096 + n0 + tx;
        out[o] = xin[o] + gamma[c] * tile[tx][ty + r * 8];
    }
}

// ---------------- bf16 tensor-core GEMM ----------------
// All operands canonical: a(i,k)=A[i*lda+k], b(k,j)=B[j*ldb+k] (both k-contiguous).
// 128x128x32 block tile, 8 warps (2x4), warp tile 64x32, mma.m16n8k16, double-buffered.
// EPI==1: exact GELU after bias.  OUTBF: write bf16 else fp32.
template<int EPI, int OUTBF>
__global__ void __launch_bounds__(256) bgemm_k(
    const bf16* __restrict__ Ag, const bf16* __restrict__ Bg,
    const float* __restrict__ bias, void* __restrict__ Cg,
    int M, int N, int K, int lda, int ldb, int ldc,
    long sA1, long sA2, long sB1, long sB2, long sC1, long sC2, int HB)
{
    int z = blockIdx.z, zo = z / HB, zi = z - zo * HB;
    const bf16* A = Ag + zo * sA1 + zi * sA2;
    const bf16* B = Bg + zo * sB1 + zi * sB2;

    __shared__ bf16 As[2][128][40];
    __shared__ bf16 Bs[2][128][40];

    int tid = threadIdx.x;
    int m0 = blockIdx.x * 128, n0 = blockIdx.y * 128;

    float c[4][4][4];
    #pragma unroll
    for (int i = 0; i < 4; i++)
        #pragma unroll
        for (int j = 0; j < 4; j++)
            #pragma unroll
            for (int q = 0; q < 4; q++) c[i][j][q] = 0.f;

    auto stage = [&](int buf, int k0) {
        int r = tid >> 2, kc = (tid & 3) * 8;
        #pragma unroll
        for (int hh = 0; hh < 2; hh++) {
            int row = r + hh * 64;
            uint4 v = make_uint4(0u, 0u, 0u, 0u);
            if (m0 + row < M) v = *(const uint4*)(A + (long)(m0 + row) * lda + k0 + kc);
            *(uint4*)(&As[buf][row][kc]) = v;
            uint4 w = make_uint4(0u, 0u, 0u, 0u);
            if (n0 + row < N) w = *(const uint4*)(B + (long)(n0 + row) * ldb + k0 + kc);
            *(uint4*)(&Bs[buf][row][kc]) = w;
        }
    };

    stage(0, 0);
    __syncthreads();

    int nst = K >> 5;
    int wid = tid >> 5, lane = tid & 31;
    int wm = wid >> 2, wn = wid & 3;
    int g = lane >> 2, t = lane & 3;
    int buf = 0;

    for (int s = 0; s < nst; s++) {
        if (s + 1 < nst) stage(buf ^ 1, (s + 1) << 5);
        #pragma unroll
        for (int ks = 0; ks < 32; ks += 16) {
            unsigned af[4][4], bfm[4][2];
            #pragma unroll
            for (int im = 0; im < 4; im++) {
                int row = wm * 64 + im * 16 + g;
                af[im][0] = *(const unsigned*)(&As[buf][row][ks + t * 2]);
                af[im][1] = *(const unsigned*)(&As[buf][row + 8][ks + t * 2]);
                af[im][2] = *(const unsigned*)(&As[buf][row][ks + 8 + t * 2]);
                af[im][3] = *(const unsigned*)(&As[buf][row + 8][ks + 8 + t * 2]);
            }
            #pragma unroll
            for (int jn = 0; jn < 4; jn++) {
                int nr = wn * 32 + jn * 8 + g;
                bfm[jn][0] = *(const unsigned*)(&Bs[buf][nr][ks + t * 2]);
                bfm[jn][1] = *(const unsigned*)(&Bs[buf][nr][ks + 8 + t * 2]);
            }
            #pragma unroll
            for (int im = 0; im < 4; im++)
                #pragma unroll
                for (int jn = 0; jn < 4; jn++)
                    asm volatile(
                        "mma.sync.aligned.m16n8k16.row.col.f32.bf16.bf16.f32 "
                        "{%0,%1,%2,%3},{%4,%5,%6,%7},{%8,%9},{%0,%1,%2,%3};\n"
                        : "+f"(c[im][jn][0]), "+f"(c[im][jn][1]),
                          "+f"(c[im][jn][2]), "+f"(c[im][jn][3])
                        : "r"(af[im][0]), "r"(af[im][1]), "r"(af[im][2]), "r"(af[im][3]),
                          "r"(bfm[jn][0]), "r"(bfm[jn][1]));
        }
        __syncthreads();
        buf ^= 1;
    }

    float* Cf = (float*)Cg + zo * sC1 + zi * sC2;
    bf16*  Cb = (bf16*)Cg + zo * sC1 + zi * sC2;
    #pragma unroll
    for (int im = 0; im < 4; im++) {
        int r0 = m0 + wm * 64 + im * 16 + g;
        #pragma unroll
        for (int jn = 0; jn < 4; jn++) {
            int col = n0 + wn * 32 + jn * 8 + t * 2;
            if (col >= N) continue;
            float b0 = bias ? bias[col] : 0.f;
            float b1 = bias ? bias[col + 1] : 0.f;
            #pragma unroll
            for (int hr = 0; hr < 2; hr++) {
                int rr = r0 + hr * 8;
                if (rr >= M) continue;
                float v0 = c[im][jn][hr * 2 + 0] + b0;
                float v1 = c[im][jn][hr * 2 + 1] + b1;
                if (EPI == 1) {
                    v0 = 0.5f * v0 * (1.0f + erff(v0 * 0.7071067811865476f));
                    v1 = 0.5f * v1 * (1.0f + erff(v1 * 0.7071067811865476f));
                }
                if (OUTBF) {
                    *(__nv_bfloat162*)(Cb + (long)rr * ldc + col) = __floats2bfloat162_rn(v0, v1);
                } else {
                    *(float2*)(Cf + (long)rr * ldc + col) = make_float2(v0, v1);
                }
            }
        }
    }
}

template<int EPI, int OUTBF>
static void bg(const bf16* A, const bf16* B, const float* bias, void* C,
               int M, int N, int K, int lda, int ldb, int ldc,
               long sA1, long sA2, long sB1, long sB2, long sC1, long sC2, int HB, int Z)
{
    dim3 grid((M + 127) / 128, (N + 127) / 128, Z);
    bgemm_k<EPI, OUTBF><<<grid, 256>>>(A, B, bias, C, M, N, K, lda, ldb, ldc,
                                       sA1, sA2, sB1, sB2, sC1, sC2, HB);
}

extern "C" void kernel_launch(void* const* d_in, const int* in_sizes, int n_in,
                              void* d_out, int out_size)
{
    const float* x          = (const float*)d_in[0];
    const float* convs_w    = (const float*)d_in[1];
    const float* convs_b    = (const float*)d_in[2];
    const float* pos_w      = (const float*)d_in[3];
    const float* pos_b      = (const float*)d_in[4];
    const float* ln_xca_w   = (const float*)d_in[5];
    const float* ln_xca_b   = (const float*)d_in[6];
    const float* gamma_xca  = (const float*)d_in[7];
    const float* xca_temp   = (const float*)d_in[8];
    const float* xca_kv_w   = (const float*)d_in[9];
    const float* xca_kv_b   = (const float*)d_in[10];
    const float* xca_proj_w = (const float*)d_in[11];
    const float* xca_proj_b = (const float*)d_in[12];
    const float* conv_out_w = (const float*)d_in[13];
    const float* conv_out_b = (const float*)d_in[14];
    const float* wa_kv_w    = (const float*)d_in[15];
    const float* wa_kv_b    = (const float*)d_in[16];
    const float* wa_proj_w  = (const float*)d_in[17];
    const float* wa_proj_b  = (const float*)d_in[18];
    const float* ln_w       = (const float*)d_in[19];
    const float* ln_b       = (const float*)d_in[20];
    const float* pw1_w      = (const float*)d_in[21];
    const float* pw1_b      = (const float*)d_in[22];
    const float* pw2_w      = (const float*)d_in[23];
    const float* pw2_b      = (const float*)d_in[24];
    const float* gamma      = (const float*)d_in[25];
    float* out = (float*)d_out;

    float *conv, *pos, *x3, *attn, *y, *norms;
    bf16 *bx, *lnb, *kv, *kt, *b1, *uqt, *battn, *h1, *wt;
    cudaGetSymbolAddress((void**)&conv,  g_conv);
    cudaGetSymbolAddress((void**)&pos,   g_pos);
    cudaGetSymbolAddress((void**)&x3,    g_x3);
    cudaGetSymbolAddress((void**)&attn,  g_attn);
    cudaGetSymbolAddress((void**)&y,     g_y);
    cudaGetSymbolAddress((void**)&norms, g_norms);
    cudaGetSymbolAddress((void**)&bx,    g_bx);
    cudaGetSymbolAddress((void**)&lnb,   g_lnb);
    cudaGetSymbolAddress((void**)&kv,    g_kv);
    cudaGetSymbolAddress((void**)&kt,    g_kt);
    cudaGetSymbolAddress((void**)&b1,    g_b1);
    cudaGetSymbolAddress((void**)&uqt,   g_uqt);
    cudaGetSymbolAddress((void**)&battn, g_battn);
    cudaGetSymbolAddress((void**)&h1,    g_h1);
    cudaGetSymbolAddress((void**)&wt,    g_wt);

    bf16* w_xkv   = wt;
    bf16* w_xproj = wt + 294912;
    bf16* w_wkv   = wt + 442368;
    bf16* w_wproj = wt + 737280;
    bf16* w_pw1   = wt + 884736;
    bf16* w_pw2   = wt + 1474560;

    // 0. conversions
    cvt_kernel<<<(25165824 + 255) / 256, 256>>>(x, bx, 25165824);
    cvt_kernel<<<(294912 + 255) / 256, 256>>>(xca_kv_w, w_xkv, 294912);
    cvt_kernel<<<(147456 + 255) / 256, 256>>>(xca_proj_w, w_xproj, 147456);
    cvt_kernel<<<(294912 + 255) / 256, 256>>>(wa_kv_w, w_wkv, 294912);
    cvt_kernel<<<(147456 + 255) / 256, 256>>>(wa_proj_w, w_wproj, 147456);
    cvt_kernel<<<(589824 + 255) / 256, 256>>>(pw1_w, w_pw1, 589824);
    cvt_kernel<<<(589824 + 255) / 256, 256>>>(pw2_w, w_pw2, 589824);

    // 1. positional features
    pos_kernel<<<4096, 384>>>(pos_w, pos_b, pos);

    // 2. Res2Net depthwise conv chain
    dim3 cg(1, 16, 16 * 96), cb(64, 4);
    dwconv_kernel<<<cg, cb>>>(x, conv, convs_w, convs_b, conv, 0);
    dwconv_kernel<<<cg, cb>>>(x, conv, convs_w, convs_b, conv, 1);
    dwconv_kernel<<<cg, cb>>>(x, conv, convs_w, convs_b, conv, 2);

    // 3. x3 = transpose + pos; uqT = unfold(inp) in [bq][c][p]
    dim3 tg(128, 12, 16), tb(32, 8);
    t1_kernel<<<tg, tb>>>(conv, x, pos, x3);
    uqt_kernel<<<(25165824 + 255) / 256, 256>>>(x, uqt);

    // 4. XCA
    ln_kernel<<<65536, 128>>>(x3, ln_xca_w, ln_xca_b, lnb, 0);
    bg<0,1>(lnb, w_xkv, xca_kv_b, kv, 65536, 768, 384, 384, 384, 768,
            0, 0, 0, 0, 0, 0, 1, 1);
    tk_kernel<<<dim3(128, 12, 16), tb>>>(kv, kt, 4096);
    norms2_k<<<768, 256>>>(kt, norms, 4096);
    // logits: A=bx[b][h*96+i][n], B=kT[b][h*96+j][n] -> attn fp32
    bg<0,0>(bx, kt, nullptr, attn, 96, 96, 4096, 4096, 4096, 96,
            (long)384*4096, (long)96*4096, (long)384*4096, (long)96*4096,
            (long)4*9216, 9216, 4, 64);
    xca_softmax_k<<<768, 256>>>(attn, norms, xca_temp, battn);
    // AV: A=v[n][d] (kv+384), B=battn[c][d] -> O1 bf16 (B,N,C)
    bg<0,1>(kv + 384, battn, nullptr, b1, 4096, 96, 96, 768, 96, 384,
            (long)4096*768, 96, (long)4*9216, 9216, (long)4096*384, 96, 4, 64);
    bg<0,1>(b1, w_xproj, xca_proj_b, conv, 65536, 384, 384, 384, 384, 384,
            0, 0, 0, 0, 0, 0, 1, 1);

    // 5. residual + conv_out + unfold scatter -> wx (bf16, reuses b1)
    e1_kernel<<<(25165824 + 255) / 256, 256>>>(x3, conv, gamma_xca, conv_out_w, conv_out_b, b1);

    // 6. Window attention
    bg<0,1>(b1, w_wkv, wa_kv_b, kv, 65536, 768, 384, 384, 384, 768,
            0, 0, 0, 0, 0, 0, 1, 1);
    tk_kernel<<<dim3(32, 12, 64), tb>>>(kv, kt, 1024);
    norms2_k<<<3072, 256>>>(kt, norms, 1024);
    bg<0,0>(uqt, kt, nullptr, attn, 96, 96, 1024, 1024, 1024, 96,
            (long)384*1024, (long)96*1024, (long)384*1024, (long)96*1024,
            (long)4*9216, 9216, 4, 256);
    wa_softmax_k<<<3072, 256>>>(attn, norms, battn);
    // AV: A=battn[c][d], B=v[nn][d] -> scrambled [h][bq][c][nn] bf16 (reuses x3 as bf16)
    bf16* x2s = (bf16*)x3;
    bg<0,1>(battn, kv + 384, nullptr, x2s, 96, 1024, 96, 96, 768, 1024,
            (long)4*9216, 9216, (long)1024*768, 96,
            (long)96*1024, (long)64*96*1024, 4, 256);
    bg<0,0>(x2s, w_wproj, wa_proj_b, conv, 65536, 384, 384, 384, 384, 384,
            0, 0, 0, 0, 0, 0, 1, 1);

    // 7. fold + LN (gather), MLP (GELU), final residual
    ln_kernel<<<65536, 128>>>(conv, ln_w, ln_b, lnb, 1);
    bg<1,1>(lnb, w_pw1, pw1_b, h1, 65536, 1536, 384, 384, 384, 1536,
            0, 0, 0, 0, 0, 0, 1, 1);
    bg<0,0>(h1, w_pw2, pw2_b, y, 65536, 384, 1536, 1536, 1536, 384,
            0, 0, 0, 0, 0, 0, 1, 1);
    final_kernel<<<tg, tb>>>(y, x, gamma, out);
}

// round 5
// speedup vs baseline: 5.2496x; 1.2174x over previous
#include <cuda_runtime.h>
#include <cuda_bf16.h>
#include <math.h>

#define FULLMASK 0xffffffffu
typedef __nv_bfloat16 bf16;
// B=16, C=384, H=W=64, N=4096, HEADS=4, HD=96

// ---------------- scratch ----------------
__device__ __align__(256) float g_conv[25165824];  // dwconv out -> wa proj out
__device__ __align__(256) float g_pos[1572864];    // [N, C]
__device__ __align__(256) float g_x3[25165824];    // x3 fp32; reused (bf16) for WA AV out
__device__ __align__(256) float g_attn[2359296];   // fp32 logits
__device__ __align__(256) float g_y[25165824];     // MLP out fp32
__device__ __align__(256) float g_norms[24576];
__device__ __align__(256) bf16 g_bx[25165824];     // bf16(x)
__device__ __align__(256) bf16 g_lnb[25165824];    // XCA LN out -> wx -> final LN out
__device__ __align__(256) bf16 g_kv[50331648];     // kv bf16
__device__ __align__(256) bf16 g_kt[25165824];     // kT bf16
__device__ __align__(256) bf16 g_b1[25165824];     // XCA AV out
__device__ __align__(256) bf16 g_uqt[25165824];    // unfold(inp) [bq][c][p]
__device__ __align__(256) bf16 g_battn[2359296];   // softmax probs bf16
__device__ __align__(256) bf16 g_h1[100663296];    // MLP hidden bf16
__device__ __align__(256) bf16 g_wt[2064384];      // converted weights

// ---------------- zero attn (for split-K atomic accumulation) ----------------
__global__ void zero_kernel(float* __restrict__ p, long n)
{
    long i = (long)blockIdx.x * 256 + threadIdx.x;
    if (i < n) p[i] = 0.f;
}

// ---------------- all weight converts in one launch ----------------
__global__ void cvtw_kernel(const float* __restrict__ s0, const float* __restrict__ s1,
                            const float* __restrict__ s2, const float* __restrict__ s3,
                            const float* __restrict__ s4, const float* __restrict__ s5,
                            bf16* __restrict__ out)
{
    long i = (long)blockIdx.x * 256 + threadIdx.x;
    if (i >= 2064384L) return;
    const float* s; long off;
    if (i < 294912)       { s = s0; off = i; }
    else if (i < 442368)  { s = s1; off = i - 294912; }
    else if (i < 737280)  { s = s2; off = i - 442368; }
    else if (i < 884736)  { s = s3; off = i - 737280; }
    else if (i < 1474560) { s = s4; off = i - 884736; }
    else                  { s = s5; off = i - 1474560; }
    out[i] = __float2bfloat16(s[off]);
}

// ---------------- x -> bf16 copy + unfold(inp) in [bq][c][p] (single read of x) ----------------
__global__ void cvtx_kernel(const float* __restrict__ x, bf16* __restrict__ bx,
                            bf16* __restrict__ uqT)
{
    long idx = (long)blockIdx.x * 256 + threadIdx.x;
    if (idx >= 25165824L) return;
    float v = x[idx];
    bf16 bv = __float2bfloat16(v);
    bx[idx] = bv;
    int n = (int)(idx & 4095);
    long r = idx >> 12;
    int c = (int)(r % 384), b = (int)(r / 384);
    int hh = n >> 6, ww = n & 63;
    int q = ((hh & 1) << 1) | (ww & 1);
    int p = ((hh >> 1) << 5) | (ww >> 1);
    uqT[((long)(b * 4 + q) * 384 + c) * 1024 + p] = bv;
}

// ---------------- positional Fourier features ----------------
__global__ void pos_kernel(const float* __restrict__ pw, const float* __restrict__ pb,
                           float* __restrict__ pos)
{
    __shared__ float feat[64];
    int n = blockIdx.x, t = threadIdx.x;
    int hh = n >> 6, ww = n & 63;
    if (t < 64) {
        int j = t, jj = j & 31, m = jj >> 1;
        float v = (j < 32) ? (float)(hh + 1) : (float)(ww + 1);
        v = v / (64.0f + 1e-6f) * 6.283185307179586f;
        float arg = v / powf(10000.0f, (float)m / 16.0f);
        feat[j] = (jj & 1) ? cosf(arg) : sinf(arg);
    }
    __syncthreads();
    float acc = pb[t];
    const float* wr = pw + t * 64;
    #pragma unroll
    for (int j = 0; j < 64; j++) acc += feat[j] * wr[j];
    pos[(long)n * 384 + t] = acc;
}

// ---------------- fused Res2Net depthwise conv chain (all 3 chunks, one block per (b,c)) ----------------
__global__ void __launch_bounds__(256) dwconv3_kernel(
    const float* __restrict__ x, const float* __restrict__ w,
    const float* __restrict__ bias, float* __restrict__ out)
{
    __shared__ float A[66 * 66], Bb[66 * 66];
    int bc = blockIdx.x, b = bc / 96, c = bc % 96, tid = threadIdx.x;
    for (int i = tid; i < 66 * 66; i += 256) { A[i] = 0.f; Bb[i] = 0.f; }
    __syncthreads();
    const float* xp = x + ((long)b * 384 + c) * 4096;
    for (int i = tid; i < 4096; i += 256)
        A[((i >> 6) + 1) * 66 + (i & 63) + 1] = xp[i];
    __syncthreads();
    float* src = A;
    float* dst = Bb;
    #pragma unroll
    for (int ch = 0; ch < 3; ch++) {
        const float* wp = w + (ch * 96 + c) * 9;
        float bv = bias[ch * 96 + c];
        float w00 = wp[0], w01 = wp[1], w02 = wp[2];
        float w10 = wp[3], w11 = wp[4], w12 = wp[5];
        float w20 = wp[6], w21 = wp[7], w22 = wp[8];
        float* op = out + ((long)b * 384 + ch * 96 + c) * 4096;
        const float* xn = (ch < 2) ? x + ((long)b * 384 + (ch + 1) * 96 + c) * 4096 : nullptr;
        for (int i = tid; i < 4096; i += 256) {
            int r = i >> 6, cc = i & 63;
            const float* p = src + r * 66 + cc;
            float acc = bv
                + w00 * p[0]   + w01 * p[1]   + w02 * p[2]
                + w10 * p[66]  + w11 * p[67]  + w12 * p[68]
                + w20 * p[132] + w21 * p[133] + w22 * p[134];
            op[i] = acc;
            if (xn) dst[(r + 1) * 66 + cc + 1] = acc + xn[i];
        }
        __syncthreads();
        float* t = src; src = dst; dst = t;
    }
}

// ---------------- transpose (B,C,N)->(B,N,C) + pos ----------------
__global__ void t1_kernel(const float* __restrict__ conv, const float* __restrict__ xin,
                          const float* __restrict__ pos, float* __restrict__ x3)
{
    __shared__ float tile[32][33];
    int n0 = blockIdx.x << 5, c0 = blockIdx.y << 5, b = blockIdx.z;
    int tx = threadIdx.x, ty = threadIdx.y;
    const float* src = (c0 >= 288) ? xin : conv;
    #pragma unroll
    for (int r = 0; r < 4; r++)
        tile[ty + r * 8][tx] = src[((long)b * 384 + c0 + ty + r * 8) * 4096 + n0 + tx];
    __syncthreads();
    #pragma unroll
    for (int r = 0; r < 4; r++) {
        int n = n0 + ty + r * 8, c = c0 + tx;
        x3[((long)b * 4096 + n) * 384 + c] = tile[tx][ty + r * 8] + pos[(long)n * 384 + c];
    }
}

// ---------------- kv k-part transpose: kv[bz][n][768](cols 0..383) -> kT[bz][d][R] ----------------
__global__ void tk_kernel(const bf16* __restrict__ kv, bf16* __restrict__ kT, int R)
{
    __shared__ bf16 tile[32][33];
    int n0 = blockIdx.x << 5, d0 = blockIdx.y << 5, bz = blockIdx.z;
    int tx = threadIdx.x, ty = threadIdx.y;
    #pragma unroll
    for (int r = 0; r < 4; r++)
        tile[ty + r * 8][tx] = kv[((long)bz * R + n0 + ty + r * 8) * 768 + d0 + tx];
    __syncthreads();
    #pragma unroll
    for (int r = 0; r < 4; r++)
        kT[((long)bz * 384 + d0 + ty + r * 8) * R + n0 + tx] = tile[tx][ty + r * 8];
}

// ---------------- L2 norms from kT (warp per (bz,d) column) ----------------
__global__ void norms2_k(const bf16* __restrict__ kT, float* __restrict__ norms, int R)
{
    int gw = blockIdx.x * 8 + (threadIdx.x >> 5);
    int lane = threadIdx.x & 31;
    const bf16* p = kT + (long)gw * R;
    float s = 0.f;
    for (int i = lane * 2; i < R; i += 64) {
        __nv_bfloat162 v = *(const __nv_bfloat162*)(p + i);
        float a = __bfloat162float(v.x), b = __bfloat162float(v.y);
        s += a * a + b * b;
    }
    #pragma unroll
    for (int o = 16; o; o >>= 1) s += __shfl_xor_sync(FULLMASK, s, o);
    if (lane == 0) norms[gw] = sqrtf(s);
}

// ---------------- LayerNorm over C=384; gather=1 applies fold() mapping; bf16 out ----------------
__global__ void ln_kernel(const float* __restrict__ in, const float* __restrict__ w,
                          const float* __restrict__ bvec, bf16* __restrict__ out, int gather)
{
    int row = blockIdx.x, t = threadIdx.x;
    long ibase;
    if (gather) {
        int b = row >> 12, n = row & 4095;
        int hh = n >> 6, ww = n & 63;
        int q = ((hh & 1) << 1) | (ww & 1);
        int p = ((hh >> 1) << 5) | (ww >> 1);
        ibase = ((long)(b * 4 + q) * 1024 + p) * 384;
    } else ibase = (long)row * 384;
    float v0 = in[ibase + t], v1 = in[ibase + t + 128], v2 = in[ibase + t + 256];
    float s = v0 + v1 + v2;
    float q2 = v0 * v0 + v1 * v1 + v2 * v2;
    #pragma unroll
    for (int o = 16; o; o >>= 1) {
        s += __shfl_down_sync(FULLMASK, s, o);
        q2 += __shfl_down_sync(FULLMASK, q2, o);
    }
    __shared__ float ss[4], sq[4], smean, srstd;
    int wid = t >> 5, lane = t & 31;
    if (lane == 0) { ss[wid] = s; sq[wid] = q2; }
    __syncthreads();
    if (t == 0) {
        float S = ss[0] + ss[1] + ss[2] + ss[3];
        float Q = sq[0] + sq[1] + sq[2] + sq[3];
        float m = S * (1.0f / 384.0f);
        smean = m;
        srstd = rsqrtf(Q * (1.0f / 384.0f) - m * m + 1e-6f);
    }
    __syncthreads();
    float m = smean, r = srstd;
    long ob = (long)row * 384;
    out[ob + t]       = __float2bfloat16((v0 - m) * r * w[t]       + bvec[t]);
    out[ob + t + 128] = __float2bfloat16((v1 - m) * r * w[t + 128] + bvec[t + 128]);
    out[ob + t + 256] = __float2bfloat16((v2 - m) * r * w[t + 256] + bvec[t + 256]);
}

// ---------------- XCA softmax over d, temp[h]/norm_d scaling; bf16 probs out ----------------
__global__ void xca_softmax_k(const float* __restrict__ G, const float* __restrict__ norms,
                              const float* __restrict__ temp, bf16* __restrict__ P)
{
    int warp = threadIdx.x >> 5, lane = threadIdx.x & 31;
    int row = blockIdx.x * 8 + warp;
    int bh = row / 96, b = bh >> 2, h = bh & 3;
    float tv = temp[h];
    const float* g = G + (long)row * 96;
    bf16* o = P + (long)row * 96;
    const float* nb = norms + b * 384 + h * 96;
    float v[3];
    #pragma unroll
    for (int i = 0; i < 3; i++) { int d = lane + i * 32; v[i] = g[d] * tv / fmaxf(nb[d], 1e-12f); }
    float m = fmaxf(v[0], fmaxf(v[1], v[2]));
    #pragma unroll
    for (int o2 = 16; o2; o2 >>= 1) m = fmaxf(m, __shfl_xor_sync(FULLMASK, m, o2));
    float e[3], s = 0.f;
    #pragma unroll
    for (int i = 0; i < 3; i++) { e[i] = expf(v[i] - m); s += e[i]; }
    #pragma unroll
    for (int o2 = 16; o2; o2 >>= 1) s += __shfl_xor_sync(FULLMASK, s, o2);
    float inv = 1.0f / s;
    #pragma unroll
    for (int i = 0; i < 3; i++) o[lane + i * 32] = __float2bfloat16(e[i] * inv);
}

// ---------------- WA double softmax; bf16 probs out ----------------
__global__ void wa_softmax_k(const float* __restrict__ G, const float* __restrict__ norms,
                             bf16* __restrict__ P)
{
    int warp = threadIdx.x >> 5, lane = threadIdx.x & 31;
    int row = blockIdx.x * 8 + warp;
    int bh = row / 96, bq = bh >> 2, h = bh & 3;
    const float* g = G + (long)row * 96;
    bf16* o = P + (long)row * 96;
    const float* nb = norms + bq * 384 + h * 96;
    float l[3];
    #pragma unroll
    for (int i = 0; i < 3; i++) { int d = lane + i * 32; l[i] = g[d] / fmaxf(nb[d], 1e-12f); }
    float m1 = fmaxf(l[0], fmaxf(l[1], l[2]));
    #pragma unroll
    for (int o2 = 16; o2; o2 >>= 1) m1 = fmaxf(m1, __shfl_xor_sync(FULLMASK, m1, o2));
    float e[3], s1 = 0.f;
    #pragma unroll
    for (int i = 0; i < 3; i++) { e[i] = expf(l[i] - m1); s1 += e[i]; }
    #pragma unroll
    for (int o2 = 16; o2; o2 >>= 1) s1 += __shfl_xor_sync(FULLMASK, s1, o2);
    float inv1 = 1.0f / s1, a[3];
    #pragma unroll
    for (int i = 0; i < 3; i++) a[i] = l[i] * 0.051031036307982884f + 0.5f * e[i] * inv1;
    float m2 = fmaxf(a[0], fmaxf(a[1], a[2]));
    #pragma unroll
    for (int o2 = 16; o2; o2 >>= 1) m2 = fmaxf(m2, __shfl_xor_sync(FULLMASK, m2, o2));
    float e2[3], s2 = 0.f;
    #pragma unroll
    for (int i = 0; i < 3; i++) { e2[i] = expf(a[i] - m2); s2 += e2[i]; }
    #pragma unroll
    for (int o2 = 16; o2; o2 >>= 1) s2 += __shfl_xor_sync(FULLMASK, s2, o2);
    float inv2 = 1.0f / s2;
    #pragma unroll
    for (int i = 0; i < 3; i++) o[lane + i * 32] = __float2bfloat16(e2[i] * inv2);
}

// ---------------- final: out[b,c,n] = inp + gamma[c]*y[b,n,c] ----------------
__global__ void final_kernel(const float* __restrict__ y, const float* __restrict__ xin,
                             const float* __restrict__ gamma, float* __restrict__ out)
{
    __shared__ float tile[32][33];
    int n0 = blockIdx.x << 5, c0 = blockIdx.y << 5, b = blockIdx.z;
    int tx = threadIdx.x, ty = threadIdx.y;
    #pragma unroll
    for (int r = 0; r < 4; r++)
        tile[ty + r * 8][tx] = y[((long)b * 4096 + n0 + ty + r * 8) * 384 + c0 + tx];
    __syncthreads();
    #pragma unroll
    for (int r = 0; r < 4; r++) {
        int c = c0 + ty + r * 8;
        long o = ((long)b * 384 + c) * 4096 + n0 + tx;
        out[o] = xin[o] + gamma[c] * tile[tx][ty + r * 8];
    }
}

// ---------------- cp.async helper ----------------
__device__ __forceinline__ void cpa16(bf16* s, const bf16* g, bool valid)
{
    unsigned sa = (unsigned)__cvta_generic_to_shared(s);
    int sz = valid ? 16 : 0;
    asm volatile("cp.async.cg.shared.global [%0], [%1], 16, %2;\n"
                 :: "r"(sa), "l"(g), "r"(sz));
}

// ---------------- bf16 tensor-core GEMM, 3-stage cp.async pipeline ----------------
// a(i,k)=A[i*lda+k], b(k,j)=B[j*ldb+k].
// EPI: 0 plain, 1 exact GELU, 2 fused e1 (residual+conv_out+unfold scatter).
// OUTBF: write bf16 else fp32.  ATOM: fp32 atomicAdd (split-K accumulate).
template<int EPI, int OUTBF, int ATOM>
__global__ void __launch_bounds__(256) bgemm_k(
    const bf16* __restrict__ Ag, const bf16* __restrict__ Bg,
    const float* __restrict__ bias, void* __restrict__ Cg,
    int M, int N, int K, int lda, int ldb, int ldc,
    long sA1, long sA2, long sB1, long sB2, long sC1, long sC2, int HB, int SK,
    const float* __restrict__ f1, const float* __restrict__ f2,
    const float* __restrict__ f3, const float* __restrict__ f4)
{
    extern __shared__ __align__(16) bf16 dyn[];
    typedef bf16 Tile[128][40];
    Tile* As = (Tile*)dyn;
    Tile* Bs = (Tile*)(dyn + 3 * 128 * 40);

    int zz = blockIdx.z;
    int ksl = zz % SK, z = zz / SK;
    int zo = z / HB, zi = z - zo * HB;
    const bf16* A = Ag + zo * sA1 + zi * sA2 + (long)ksl * K;
    const bf16* B = Bg + zo * sB1 + zi * sB2 + (long)ksl * K;

    int tid = threadIdx.x;
    int m0 = blockIdx.x * 128, n0 = blockIdx.y * 128;

    float c[4][4][4];
    #pragma unroll
    for (int i = 0; i < 4; i++)
        #pragma unroll
        for (int j = 0; j < 4; j++)
            #pragma unroll
            for (int q = 0; q < 4; q++) c[i][j][q] = 0.f;

    int rS = tid >> 2, kcS = (tid & 3) * 8;
    auto stage = [&](int buf, int k0) {
        #pragma unroll
        for (int hh = 0; hh < 2; hh++) {
            int row = rS + hh * 64;
            int ra = m0 + row < M ? m0 + row : M - 1;
            cpa16(&As[buf][row][kcS], A + (long)ra * lda + k0 + kcS, m0 + row < M);
            int rb = n0 + row < N ? n0 + row : N - 1;
            cpa16(&Bs[buf][row][kcS], B + (long)rb * ldb + k0 + kcS, n0 + row < N);
        }
    };

    int nst = K >> 5;
    stage(0, 0);
    asm volatile("cp.async.commit_group;\n");
    if (nst > 1) stage(1, 32);
    asm volatile("cp.async.commit_group;\n");

    int wid = tid >> 5, lane = tid & 31;
    int wm = wid >> 2, wn = wid & 3;
    int g = lane >> 2, t = lane & 3;

    for (int s = 0; s < nst; s++) {
        asm volatile("cp.async.wait_group 1;\n");
        __syncthreads();
        int nf = s + 2;
        if (nf < nst) stage(nf % 3, nf << 5);
        asm volatile("cp.async.commit_group;\n");
        int buf = s % 3;
        #pragma unroll
        for (int ks = 0; ks < 32; ks += 16) {
            unsigned af[4][4], bfm[4][2];
            #pragma unroll
            for (int im = 0; im < 4; im++) {
                int row = wm * 64 + im * 16 + g;
                af[im][0] = *(const unsigned*)(&As[buf][row][ks + t * 2]);
                af[im][1] = *(const unsigned*)(&As[buf][row + 8][ks + t * 2]);
                af[im][2] = *(const unsigned*)(&As[buf][row][ks + 8 + t * 2]);
                af[im][3] = *(const unsigned*)(&As[buf][row + 8][ks + 8 + t * 2]);
            }
            #pragma unroll
            for (int jn = 0; jn < 4; jn++) {
                int nr = wn * 32 + jn * 8 + g;
                bfm[jn][0] = *(const unsigned*)(&Bs[buf][nr][ks + t * 2]);
                bfm[jn][1] = *(const unsigned*)(&Bs[buf][nr][ks + 8 + t * 2]);
            }
            #pragma unroll
            for (int im = 0; im < 4; im++)
                #pragma unroll
                for (int jn = 0; jn < 4; jn++)
                    asm volatile(
                        "mma.sync.aligned.m16n8k16.row.col.f32.bf16.bf16.f32 "
                        "{%0,%1,%2,%3},{%4,%5,%6,%7},{%8,%9},{%0,%1,%2,%3};\n"
                        : "+f"(c[im][jn][0]), "+f"(c[im][jn][1]),
                          "+f"(c[im][jn][2]), "+f"(c[im][jn][3])
                        : "r"(af[im][0]), "r"(af[im][1]), "r"(af[im][2]), "r"(af[im][3]),
                          "r"(bfm[jn][0]), "r"(bfm[jn][1]));
        }
        __syncthreads();
    }

    float* Cf = (float*)Cg + zo * sC1 + zi * sC2;
    bf16*  Cb = (bf16*)Cg + zo * sC1 + zi * sC2;
    #pragma unroll
    for (int im = 0; im < 4; im++) {
        int r0 = m0 + wm * 64 + im * 16 + g;
        #pragma unroll
        for (int jn = 0; jn < 4; jn++) {
            int col = n0 + wn * 32 + jn * 8 + t * 2;
            if (col >= N) continue;
            float b0 = bias ? bias[col] : 0.f;
            float b1 = bias ? bias[col + 1] : 0.f;
            #pragma unroll
            for (int hr = 0; hr < 2; hr++) {
                int rr = r0 + hr * 8;
                if (rr >= M) continue;
                float v0 = c[im][jn][hr * 2 + 0] + b0;
                float v1 = c[im][jn][hr * 2 + 1] + b1;
                if (EPI == 1) {
                    v0 = 0.5f * v0 * (1.0f + erff(v0 * 0.7071067811865476f));
                    v1 = 0.5f * v1 * (1.0f + erff(v1 * 0.7071067811865476f));
                }
                if (EPI == 2) {
                    // v = (x3 + gamma_xca*xca)*conv_w + conv_b, scattered to [bq][p][c]
                    long rb = (long)rr * 384 + col;
                    float a0 = (f1[rb]     + f2[col]     * v0) * f3[col]     + f4[col];
                    float a1 = (f1[rb + 1] + f2[col + 1] * v1) * f3[col + 1] + f4[col + 1];
                    int n = rr & 4095, b = rr >> 12;
                    int hh2 = n >> 6, ww2 = n & 63;
                    int q = ((hh2 & 1) << 1) | (ww2 & 1);
                    int p = ((hh2 >> 1) << 5) | (ww2 >> 1);
                    bf16* dst = (bf16*)Cg + ((long)(b * 4 + q) * 1024 + p) * 384 + col;
                    *(__nv_bfloat162*)dst = __floats2bfloat162_rn(a0, a1);
                } else if (ATOM) {
                    atomicAdd(&Cf[(long)rr * ldc + col], v0);
                    atomicAdd(&Cf[(long)rr * ldc + col + 1], v1);
                } else if (OUTBF) {
                    *(__nv_bfloat162*)(Cb + (long)rr * ldc + col) = __floats2bfloat162_rn(v0, v1);
                } else {
                    *(float2*)(Cf + (long)rr * ldc + col) = make_float2(v0, v1);
                }
            }
        }
    }
}

template<int EPI, int OUTBF, int ATOM>
static void bg(const bf16* A, const bf16* B, const float* bias, void* C,
               int M, int N, int K, int lda, int ldb, int ldc,
               long sA1, long sA2, long sB1, long sB2, long sC1, long sC2,
               int HB, int Z, int SK = 1,
               const float* f1 = nullptr, const float* f2 = nullptr,
               const float* f3 = nullptr, const float* f4 = nullptr)
{
    cudaFuncSetAttribute(bgemm_k<EPI, OUTBF, ATOM>,
                         cudaFuncAttributeMaxDynamicSharedMemorySize, 61440);
    dim3 grid((M + 127) / 128, (N + 127) / 128, Z * SK);
    bgemm_k<EPI, OUTBF, ATOM><<<grid, 256, 61440>>>(
        A, B, bias, C, M, N, K / SK, lda, ldb, ldc,
        sA1, sA2, sB1, sB2, sC1, sC2, HB, SK, f1, f2, f3, f4);
}

extern "C" void kernel_launch(void* const* d_in, const int* in_sizes, int n_in,
                              void* d_out, int out_size)
{
    const float* x          = (const float*)d_in[0];
    const float* convs_w    = (const float*)d_in[1];
    const float* convs_b    = (const float*)d_in[2];
    const float* pos_w      = (const float*)d_in[3];
    const float* pos_b      = (const float*)d_in[4];
    const float* ln_xca_w   = (const float*)d_in[5];
    const float* ln_xca_b   = (const float*)d_in[6];
    const float* gamma_xca  = (const float*)d_in[7];
    const float* xca_temp   = (const float*)d_in[8];
    const float* xca_kv_w   = (const float*)d_in[9];
    const float* xca_kv_b   = (const float*)d_in[10];
    const float* xca_proj_w = (const float*)d_in[11];
    const float* xca_proj_b = (const float*)d_in[12];
    const float* conv_out_w = (const float*)d_in[13];
    const float* conv_out_b = (const float*)d_in[14];
    const float* wa_kv_w    = (const float*)d_in[15];
    const float* wa_kv_b    = (const float*)d_in[16];
    const float* wa_proj_w  = (const float*)d_in[17];
    const float* wa_proj_b  = (const float*)d_in[18];
    const float* ln_w       = (const float*)d_in[19];
    const float* ln_b       = (const float*)d_in[20];
    const float* pw1_w      = (const float*)d_in[21];
    const float* pw1_b      = (const float*)d_in[22];
    const float* pw2_w      = (const float*)d_in[23];
    const float* pw2_b      = (const float*)d_in[24];
    const float* gamma      = (const float*)d_in[25];
    float* out = (float*)d_out;

    float *conv, *pos, *x3, *attn, *y, *norms;
    bf16 *bx, *lnb, *kv, *kt, *b1, *uqt, *battn, *h1, *wt;
    cudaGetSymbolAddress((void**)&conv,  g_conv);
    cudaGetSymbolAddress((void**)&pos,   g_pos);
    cudaGetSymbolAddress((void**)&x3,    g_x3);
    cudaGetSymbolAddress((void**)&attn,  g_attn);
    cudaGetSymbolAddress((void**)&y,     g_y);
    cudaGetSymbolAddress((void**)&norms, g_norms);
    cudaGetSymbolAddress((void**)&bx,    g_bx);
    cudaGetSymbolAddress((void**)&lnb,   g_lnb);
    cudaGetSymbolAddress((void**)&kv,    g_kv);
    cudaGetSymbolAddress((void**)&kt,    g_kt);
    cudaGetSymbolAddress((void**)&b1,    g_b1);
    cudaGetSymbolAddress((void**)&uqt,   g_uqt);
    cudaGetSymbolAddress((void**)&battn, g_battn);
    cudaGetSymbolAddress((void**)&h1,    g_h1);
    cudaGetSymbolAddress((void**)&wt,    g_wt);

    bf16* w_xkv   = wt;
    bf16* w_xproj = wt + 294912;
    bf16* w_wkv   = wt + 442368;
    bf16* w_wproj = wt + 737280;
    bf16* w_pw1   = wt + 884736;
    bf16* w_pw2   = wt + 1474560;

    // 0. conversions + unfold(inp)
    cvtw_kernel<<<(2064384 + 255) / 256, 256>>>(xca_kv_w, xca_proj_w, wa_kv_w,
                                                wa_proj_w, pw1_w, pw2_w, wt);
    cvtx_kernel<<<(25165824 + 255) / 256, 256>>>(x, bx, uqt);

    // 1. positional features + fused dwconv chain
    pos_kernel<<<4096, 384>>>(pos_w, pos_b, pos);
    dwconv3_kernel<<<16 * 96, 256>>>(x, convs_w, convs_b, conv);

    // 2. x3 = transpose + pos
    dim3 tg(128, 12, 16), tb(32, 8);
    t1_kernel<<<tg, tb>>>(conv, x, pos, x3);

    // 3. XCA
    ln_kernel<<<65536, 128>>>(x3, ln_xca_w, ln_xca_b, lnb, 0);
    bg<0,1,0>(lnb, w_xkv, xca_kv_b, kv, 65536, 768, 384, 384, 384, 768,
              0, 0, 0, 0, 0, 0, 1, 1);
    tk_kernel<<<dim3(128, 12, 16), tb>>>(kv, kt, 4096);
    norms2_k<<<768, 256>>>(kt, norms, 4096);
    zero_kernel<<<(589824 + 255) / 256, 256>>>(attn, 589824);
    // logits split-K=4, atomic accumulate
    bg<0,0,1>(bx, kt, nullptr, attn, 96, 96, 4096, 4096, 4096, 96,
              (long)384*4096, (long)96*4096, (long)384*4096, (long)96*4096,
              (long)4*9216, 9216, 4, 64, 4);
    xca_softmax_k<<<768, 256>>>(attn, norms, xca_temp, battn);
    bg<0,1,0>(kv + 384, battn, nullptr, b1, 4096, 96, 96, 768, 96, 384,
              (long)4096*768, 96, (long)4*9216, 9216, (long)4096*384, 96, 4, 64);
    // proj + fused e1: writes wx (scattered bf16) into lnb
    bg<2,1,0>(b1, w_xproj, xca_proj_b, lnb, 65536, 384, 384, 384, 384, 384,
              0, 0, 0, 0, 0, 0, 1, 1, 1, x3, gamma_xca, conv_out_w, conv_out_b);

    // 4. Window attention (wx = lnb)
    bg<0,1,0>(lnb, w_wkv, wa_kv_b, kv, 65536, 768, 384, 384, 384, 768,
              0, 0, 0, 0, 0, 0, 1, 1);
    tk_kernel<<<dim3(32, 12, 64), tb>>>(kv, kt, 1024);
    norms2_k<<<3072, 256>>>(kt, norms, 1024);
    bg<0,0,0>(uqt, kt, nullptr, attn, 96, 96, 1024, 1024, 1024, 96,
              (long)384*1024, (long)96*1024, (long)384*1024, (long)96*1024,
              (long)4*9216, 9216, 4, 256);
    wa_softmax_k<<<3072, 256>>>(attn, norms, battn);
    bf16* x2s = (bf16*)x3;
    bg<0,1,0>(battn, kv + 384, nullptr, x2s, 96, 1024, 96, 96, 768, 1024,
              (long)4*9216, 9216, (long)1024*768, 96,
              (long)96*1024, (long)64*96*1024, 4, 256);
    bg<0,0,0>(x2s, w_wproj, wa_proj_b, conv, 65536, 384, 384, 384, 384, 384,
              0, 0, 0, 0, 0, 0, 1, 1);

    // 5. fold + LN (gather), MLP (GELU), final residual
    ln_kernel<<<65536, 128>>>(conv, ln_w, ln_b, lnb, 1);
    bg<1,1,0>(lnb, w_pw1, pw1_b, h1, 65536, 1536, 384, 384, 384, 1536,
              0, 0, 0, 0, 0, 0, 1, 1);
    bg<0,0,0>(h1, w_pw2, pw2_b, y, 65536, 384, 1536, 1536, 1536, 384,
              0, 0, 0, 0, 0, 0, 1, 1);
    final_kernel<<<tg, tb>>>(y, x, gamma, out);
}

// round 6
// speedup vs baseline: 5.3068x; 1.0109x over previous
#include <cuda_runtime.h>
#include <cuda_bf16.h>
#include <math.h>

#define FULLMASK 0xffffffffu
typedef __nv_bfloat16 bf16;
// B=16, C=384, H=W=64, N=4096, HEADS=4, HD=96

// ---------------- scratch ----------------
__device__ __align__(256) float g_conv[25165824];
__device__ __align__(256) float g_pos[1572864];
__device__ __align__(256) float g_x3[25165824];
__device__ __align__(256) float g_attn[2359296];
__device__ __align__(256) float g_y[25165824];
__device__ __align__(256) float g_norms[24576];
__device__ __align__(256) bf16 g_bx[25165824];
__device__ __align__(256) bf16 g_lnb[25165824];
__device__ __align__(256) bf16 g_kv[50331648];
__device__ __align__(256) bf16 g_kt[25165824];
__device__ __align__(256) bf16 g_b1[25165824];
__device__ __align__(256) bf16 g_uqt[25165824];
__device__ __align__(256) bf16 g_battn[2359296];
__device__ __align__(256) bf16 g_h1[100663296];
__device__ __align__(256) bf16 g_wt[2064384];

__global__ void zero_kernel(float* __restrict__ p, long n)
{
    long i = (long)blockIdx.x * 256 + threadIdx.x;
    if (i < n) p[i] = 0.f;
}

__global__ void cvtw_kernel(const float* __restrict__ s0, const float* __restrict__ s1,
                            const float* __restrict__ s2, const float* __restrict__ s3,
                            const float* __restrict__ s4, const float* __restrict__ s5,
                            bf16* __restrict__ out)
{
    long i = (long)blockIdx.x * 256 + threadIdx.x;
    if (i >= 2064384L) return;
    const float* s; long off;
    if (i < 294912)       { s = s0; off = i; }
    else if (i < 442368)  { s = s1; off = i - 294912; }
    else if (i < 737280)  { s = s2; off = i - 442368; }
    else if (i < 884736)  { s = s3; off = i - 737280; }
    else if (i < 1474560) { s = s4; off = i - 884736; }
    else                  { s = s5; off = i - 1474560; }
    out[i] = __float2bfloat16(s[off]);
}

__global__ void cvtx_kernel(const float* __restrict__ x, bf16* __restrict__ bx,
                            bf16* __restrict__ uqT)
{
    long idx = (long)blockIdx.x * 256 + threadIdx.x;
    if (idx >= 25165824L) return;
    float v = x[idx];
    bf16 bv = __float2bfloat16(v);
    bx[idx] = bv;
    int n = (int)(idx & 4095);
    long r = idx >> 12;
    int c = (int)(r % 384), b = (int)(r / 384);
    int hh = n >> 6, ww = n & 63;
    int q = ((hh & 1) << 1) | (ww & 1);
    int p = ((hh >> 1) << 5) | (ww >> 1);
    uqT[((long)(b * 4 + q) * 384 + c) * 1024 + p] = bv;
}

__global__ void pos_kernel(const float* __restrict__ pw, const float* __restrict__ pb,
                           float* __restrict__ pos)
{
    __shared__ float feat[64];
    int n = blockIdx.x, t = threadIdx.x;
    int hh = n >> 6, ww = n & 63;
    if (t < 64) {
        int j = t, jj = j & 31, m = jj >> 1;
        float v = (j < 32) ? (float)(hh + 1) : (float)(ww + 1);
        v = v / (64.0f + 1e-6f) * 6.283185307179586f;
        float arg = v / powf(10000.0f, (float)m / 16.0f);
        feat[j] = (jj & 1) ? cosf(arg) : sinf(arg);
    }
    __syncthreads();
    float acc = pb[t];
    const float* wr = pw + t * 64;
    #pragma unroll
    for (int j = 0; j < 64; j++) acc += feat[j] * wr[j];
    pos[(long)n * 384 + t] = acc;
}

__global__ void __launch_bounds__(256) dwconv3_kernel(
    const float* __restrict__ x, const float* __restrict__ w,
    const float* __restrict__ bias, float* __restrict__ out)
{
    __shared__ float A[66 * 66], Bb[66 * 66];
    int bc = blockIdx.x, b = bc / 96, c = bc % 96, tid = threadIdx.x;
    for (int i = tid; i < 66 * 66; i += 256) { A[i] = 0.f; Bb[i] = 0.f; }
    __syncthreads();
    const float* xp = x + ((long)b * 384 + c) * 4096;
    for (int i = tid; i < 4096; i += 256)
        A[((i >> 6) + 1) * 66 + (i & 63) + 1] = xp[i];
    __syncthreads();
    float* src = A;
    float* dst = Bb;
    #pragma unroll
    for (int ch = 0; ch < 3; ch++) {
        const float* wp = w + (ch * 96 + c) * 9;
        float bv = bias[ch * 96 + c];
        float w00 = wp[0], w01 = wp[1], w02 = wp[2];
        float w10 = wp[3], w11 = wp[4], w12 = wp[5];
        float w20 = wp[6], w21 = wp[7], w22 = wp[8];
        float* op = out + ((long)b * 384 + ch * 96 + c) * 4096;
        const float* xn = (ch < 2) ? x + ((long)b * 384 + (ch + 1) * 96 + c) * 4096 : nullptr;
        for (int i = tid; i < 4096; i += 256) {
            int r = i >> 6, cc = i & 63;
            const float* p = src + r * 66 + cc;
            float acc = bv
                + w00 * p[0]   + w01 * p[1]   + w02 * p[2]
                + w10 * p[66]  + w11 * p[67]  + w12 * p[68]
                + w20 * p[132] + w21 * p[133] + w22 * p[134];
            op[i] = acc;
            if (xn) dst[(r + 1) * 66 + cc + 1] = acc + xn[i];
        }
        __syncthreads();
        float* t = src; src = dst; dst = t;
    }
}

__global__ void t1_kernel(const float* __restrict__ conv, const float* __restrict__ xin,
                          const float* __restrict__ pos, float* __restrict__ x3)
{
    __shared__ float tile[32][33];
    int n0 = blockIdx.x << 5, c0 = blockIdx.y << 5, b = blockIdx.z;
    int tx = threadIdx.x, ty = threadIdx.y;
    const float* src = (c0 >= 288) ? xin : conv;
    #pragma unroll
    for (int r = 0; r < 4; r++)
        tile[ty + r * 8][tx] = src[((long)b * 384 + c0 + ty + r * 8) * 4096 + n0 + tx];
    __syncthreads();
    #pragma unroll
    for (int r = 0; r < 4; r++) {
        int n = n0 + ty + r * 8, c = c0 + tx;
        x3[((long)b * 4096 + n) * 384 + c] = tile[tx][ty + r * 8] + pos[(long)n * 384 + c];
    }
}

__global__ void tk_kernel(const bf16* __restrict__ kv, bf16* __restrict__ kT, int R)
{
    __shared__ bf16 tile[32][33];
    int n0 = blockIdx.x << 5, d0 = blockIdx.y << 5, bz = blockIdx.z;
    int tx = threadIdx.x, ty = threadIdx.y;
    #pragma unroll
    for (int r = 0; r < 4; r++)
        tile[ty + r * 8][tx] = kv[((long)bz * R + n0 + ty + r * 8) * 768 + d0 + tx];
    __syncthreads();
    #pragma unroll
    for (int r = 0; r < 4; r++)
        kT[((long)bz * 384 + d0 + ty + r * 8) * R + n0 + tx] = tile[tx][ty + r * 8];
}

__global__ void norms2_k(const bf16* __restrict__ kT, float* __restrict__ norms, int R)
{
    int gw = blockIdx.x * 8 + (threadIdx.x >> 5);
    int lane = threadIdx.x & 31;
    const bf16* p = kT + (long)gw * R;
    float s = 0.f;
    for (int i = lane * 2; i < R; i += 64) {
        __nv_bfloat162 v = *(const __nv_bfloat162*)(p + i);
        float a = __bfloat162float(v.x), b = __bfloat162float(v.y);
        s += a * a + b * b;
    }
    #pragma unroll
    for (int o = 16; o; o >>= 1) s += __shfl_xor_sync(FULLMASK, s, o);
    if (lane == 0) norms[gw] = sqrtf(s);
}

__global__ void ln_kernel(const float* __restrict__ in, const float* __restrict__ w,
                          const float* __restrict__ bvec, bf16* __restrict__ out, int gather)
{
    int row = blockIdx.x, t = threadIdx.x;
    long ibase;
    if (gather) {
        int b = row >> 12, n = row & 4095;
        int hh = n >> 6, ww = n & 63;
        int q = ((hh & 1) << 1) | (ww & 1);
        int p = ((hh >> 1) << 5) | (ww >> 1);
        ibase = ((long)(b * 4 + q) * 1024 + p) * 384;
    } else ibase = (long)row * 384;
    float v0 = in[ibase + t], v1 = in[ibase + t + 128], v2 = in[ibase + t + 256];
    float s = v0 + v1 + v2;
    float q2 = v0 * v0 + v1 * v1 + v2 * v2;
    #pragma unroll
    for (int o = 16; o; o >>= 1) {
        s += __shfl_down_sync(FULLMASK, s, o);
        q2 += __shfl_down_sync(FULLMASK, q2, o);
    }
    __shared__ float ss[4], sq[4], smean, srstd;
    int wid = t >> 5, lane = t & 31;
    if (lane == 0) { ss[wid] = s; sq[wid] = q2; }
    __syncthreads();
    if (t == 0) {
        float S = ss[0] + ss[1] + ss[2] + ss[3];
        float Q = sq[0] + sq[1] + sq[2] + sq[3];
        float m = S * (1.0f / 384.0f);
        smean = m;
        srstd = rsqrtf(Q * (1.0f / 384.0f) - m * m + 1e-6f);
    }
    __syncthreads();
    float m = smean, r = srstd;
    long ob = (long)row * 384;
    out[ob + t]       = __float2bfloat16((v0 - m) * r * w[t]       + bvec[t]);
    out[ob + t + 128] = __float2bfloat16((v1 - m) * r * w[t + 128] + bvec[t + 128]);
    out[ob + t + 256] = __float2bfloat16((v2 - m) * r * w[t + 256] + bvec[t + 256]);
}

__global__ void xca_softmax_k(const float* __restrict__ G, const float* __restrict__ norms,
                              const float* __restrict__ temp, bf16* __restrict__ P)
{
    int warp = threadIdx.x >> 5, lane = threadIdx.x & 31;
    int row = blockIdx.x * 8 + warp;
    int bh = row / 96, b = bh >> 2, h = bh & 3;
    float tv = temp[h];
    const float* g = G + (long)row * 96;
    bf16* o = P + (long)row * 96;
    const float* nb = norms + b * 384 + h * 96;
    float v[3];
    #pragma unroll
    for (int i = 0; i < 3; i++) { int d = lane + i * 32; v[i] = g[d] * tv / fmaxf(nb[d], 1e-12f); }
    float m = fmaxf(v[0], fmaxf(v[1], v[2]));
    #pragma unroll
    for (int o2 = 16; o2; o2 >>= 1) m = fmaxf(m, __shfl_xor_sync(FULLMASK, m, o2));
    float e[3], s = 0.f;
    #pragma unroll
    for (int i = 0; i < 3; i++) { e[i] = expf(v[i] - m); s += e[i]; }
    #pragma unroll
    for (int o2 = 16; o2; o2 >>= 1) s += __shfl_xor_sync(FULLMASK, s, o2);
    float inv = 1.0f / s;
    #pragma unroll
    for (int i = 0; i < 3; i++) o[lane + i * 32] = __float2bfloat16(e[i] * inv);
}

__global__ void wa_softmax_k(const float* __restrict__ G, const float* __restrict__ norms,
                             bf16* __restrict__ P)
{
    int warp = threadIdx.x >> 5, lane = threadIdx.x & 31;
    int row = blockIdx.x * 8 + warp;
    int bh = row / 96, bq = bh >> 2, h = bh & 3;
    const float* g = G + (long)row * 96;
    bf16* o = P + (long)row * 96;
    const float* nb = norms + bq * 384 + h * 96;
    float l[3];
    #pragma unroll
    for (int i = 0; i < 3; i++) { int d = lane + i * 32; l[i] = g[d] / fmaxf(nb[d], 1e-12f); }
    float m1 = fmaxf(l[0], fmaxf(l[1], l[2]));
    #pragma unroll
    for (int o2 = 16; o2; o2 >>= 1) m1 = fmaxf(m1, __shfl_xor_sync(FULLMASK, m1, o2));
    float e[3], s1 = 0.f;
    #pragma unroll
    for (int i = 0; i < 3; i++) { e[i] = expf(l[i] - m1); s1 += e[i]; }
    #pragma unroll
    for (int o2 = 16; o2; o2 >>= 1) s1 += __shfl_xor_sync(FULLMASK, s1, o2);
    float inv1 = 1.0f / s1, a[3];
    #pragma unroll
    for (int i = 0; i < 3; i++) a[i] = l[i] * 0.051031036307982884f + 0.5f * e[i] * inv1;
    float m2 = fmaxf(a[0], fmaxf(a[1], a[2]));
    #pragma unroll
    for (int o2 = 16; o2; o2 >>= 1) m2 = fmaxf(m2, __shfl_xor_sync(FULLMASK, m2, o2));
    float e2[3], s2 = 0.f;
    #pragma unroll
    for (int i = 0; i < 3; i++) { e2[i] = expf(a[i] - m2); s2 += e2[i]; }
    #pragma unroll
    for (int o2 = 16; o2; o2 >>= 1) s2 += __shfl_xor_sync(FULLMASK, s2, o2);
    float inv2 = 1.0f / s2;
    #pragma unroll
    for (int i = 0; i < 3; i++) o[lane + i * 32] = __float2bfloat16(e2[i] * inv2);
}

__global__ void final_kernel(const float* __restrict__ y, const float* __restrict__ xin,
                             const float* __restrict__ gamma, float* __restrict__ out)
{
    __shared__ float tile[32][33];
    int n0 = blockIdx.x << 5, c0 = blockIdx.y << 5, b = blockIdx.z;
    int tx = threadIdx.x, ty = threadIdx.y;
    #pragma unroll
    for (int r = 0; r < 4; r++)
        tile[ty + r * 8][tx] = y[((long)b * 4096 + n0 + ty + r * 8) * 384 + c0 + tx];
    __syncthreads();
    #pragma unroll
    for (int r = 0; r < 4; r++) {
        int c = c0 + ty + r * 8;
        long o = ((long)b * 384 + c) * 4096 + n0 + tx;
        out[o] = xin[o] + gamma[c] * tile[tx][ty + r * 8];
    }
}

__device__ __forceinline__ void cpa16(bf16* s, const bf16* g, bool valid)
{
    unsigned sa = (unsigned)__cvta_generic_to_shared(s);
    int sz = valid ? 16 : 0;
    asm volatile("cp.async.cg.shared.global [%0], [%1], 16, %2;\n"
                 :: "r"(sa), "l"(g), "r"(sz));
}

// ---------------- bf16 tensor-core GEMM, 3-stage cp.async + ldmatrix ----------------
// a(i,k)=A[i*lda+k], b(k,j)=B[j*ldb+k].
// EPI: 0 plain, 1 exact GELU, 2 fused e1.  OUTBF: bf16 out.  ATOM: fp32 atomicAdd.
template<int EPI, int OUTBF, int ATOM>
__global__ void __launch_bounds__(256) bgemm_k(
    const bf16* __restrict__ Ag, const bf16* __restrict__ Bg,
    const float* __restrict__ bias, void* __restrict__ Cg,
    int M, int N, int K, int lda, int ldb, int ldc,
    long sA1, long sA2, long sB1, long sB2, long sC1, long sC2, int HB, int SK,
    const float* __restrict__ f1, const float* __restrict__ f2,
    const float* __restrict__ f3, const float* __restrict__ f4)
{
    extern __shared__ __align__(16) bf16 dyn[];
    const int TE = 128 * 40;                 // elems per tile
    bf16* Asp = dyn;                         // 3 A tiles
    bf16* Bsp = dyn + 3 * TE;                // 3 B tiles
    unsigned sbA = (unsigned)__cvta_generic_to_shared(Asp);
    unsigned sbB = (unsigned)__cvta_generic_to_shared(Bsp);

    int zz = blockIdx.z;
    int ksl = zz % SK, z = zz / SK;
    int zo = z / HB, zi = z - zo * HB;
    const bf16* A = Ag + zo * sA1 + zi * sA2 + (long)ksl * K;
    const bf16* B = Bg + zo * sB1 + zi * sB2 + (long)ksl * K;

    int tid = threadIdx.x;
    int m0 = blockIdx.x * 128, n0 = blockIdx.y * 128;

    float c[4][4][4];
    #pragma unroll
    for (int i = 0; i < 4; i++)
        #pragma unroll
        for (int j = 0; j < 4; j++)
            #pragma unroll
            for (int q = 0; q < 4; q++) c[i][j][q] = 0.f;

    int rS = tid >> 2, kcS = (tid & 3) * 8;
    auto stage = [&](int buf, int k0) {
        #pragma unroll
        for (int hh = 0; hh < 2; hh++) {
            int row = rS + hh * 64;
            int ra = m0 + row < M ? m0 + row : M - 1;
            cpa16(Asp + buf * TE + row * 40 + kcS, A + (long)ra * lda + k0 + kcS, m0 + row < M);
            int rb = n0 + row < N ? n0 + row : N - 1;
            cpa16(Bsp + buf * TE + row * 40 + kcS, B + (long)rb * ldb + k0 + kcS, n0 + row < N);
        }
    };

    int nst = K >> 5;
    stage(0, 0);
    asm volatile("cp.async.commit_group;\n");
    if (nst > 1) stage(1, 32);
    asm volatile("cp.async.commit_group;\n");

    int wid = tid >> 5, lane = tid & 31;
    int wm = wid >> 2, wn = wid & 3;
    int g = lane >> 2, t = lane & 3;
    // ldmatrix lane-address components
    int aRow = ((lane >> 3) & 1) * 8 + (lane & 7);   // row within 16
    int aK = (lane >> 4) * 8;                        // k-half select
    int l16 = lane & 15;
    int bRow = l16 & 7;
    int bK = ((l16 >> 3) & 1) * 8;

    for (int s = 0; s < nst; s++) {
        int nf = s + 2;
        if (nf < nst) stage(nf % 3, nf << 5);
        asm volatile("cp.async.commit_group;\n");
        asm volatile("cp.async.wait_group 2;\n");
        __syncthreads();
        int buf = s % 3;
        unsigned aT = sbA + buf * TE * 2;
        unsigned bT = sbB + buf * TE * 2;
        #pragma unroll
        for (int ks = 0; ks < 32; ks += 16) {
            unsigned af[4][4], bfm[4][2];
            #pragma unroll
            for (int im = 0; im < 4; im++) {
                unsigned addr = aT + (((wm * 64 + im * 16 + aRow) * 40) + ks + aK) * 2;
                asm volatile("ldmatrix.sync.aligned.m8n8.x4.shared.b16 {%0,%1,%2,%3}, [%4];\n"
                             : "=r"(af[im][0]), "=r"(af[im][1]), "=r"(af[im][2]), "=r"(af[im][3])
                             : "r"(addr));
            }
            #pragma unroll
            for (int jn = 0; jn < 4; jn++) {
                unsigned addr = bT + (((wn * 32 + jn * 8 + bRow) * 40) + ks + bK) * 2;
                asm volatile("ldmatrix.sync.aligned.m8n8.x2.shared.b16 {%0,%1}, [%2];\n"
                             : "=r"(bfm[jn][0]), "=r"(bfm[jn][1])
                             : "r"(addr));
            }
            #pragma unroll
            for (int im = 0; im < 4; im++)
                #pragma unroll
                for (int jn = 0; jn < 4; jn++)
                    asm volatile(
                        "mma.sync.aligned.m16n8k16.row.col.f32.bf16.bf16.f32 "
                        "{%0,%1,%2,%3},{%4,%5,%6,%7},{%8,%9},{%0,%1,%2,%3};\n"
                        : "+f"(c[im][jn][0]), "+f"(c[im][jn][1]),
                          "+f"(c[im][jn][2]), "+f"(c[im][jn][3])
                        : "r"(af[im][0]), "r"(af[im][1]), "r"(af[im][2]), "r"(af[im][3]),
                          "r"(bfm[jn][0]), "r"(bfm[jn][1]));
        }
        __syncthreads();
    }

    float* Cf = (float*)Cg + zo * sC1 + zi * sC2;
    bf16*  Cb = (bf16*)Cg + zo * sC1 + zi * sC2;
    #pragma unroll
    for (int im = 0; im < 4; im++) {
        int r0 = m0 + wm * 64 + im * 16 + g;
        #pragma unroll
        for (int jn = 0; jn < 4; jn++) {
            int col = n0 + wn * 32 + jn * 8 + t * 2;
            if (col >= N) continue;
            float b0 = bias ? bias[col] : 0.f;
            float b1 = bias ? bias[col + 1] : 0.f;
            #pragma unroll
            for (int hr = 0; hr < 2; hr++) {
                int rr = r0 + hr * 8;
                if (rr >= M) continue;
                float v0 = c[im][jn][hr * 2 + 0] + b0;
                float v1 = c[im][jn][hr * 2 + 1] + b1;
                if (EPI == 1) {
                    v0 = 0.5f * v0 * (1.0f + erff(v0 * 0.7071067811865476f));
                    v1 = 0.5f * v1 * (1.0f + erff(v1 * 0.7071067811865476f));
                }
                if (EPI == 2) {
                    long rb = (long)rr * 384 + col;
                    float a0 = (f1[rb]     + f2[col]     * v0) * f3[col]     + f4[col];
                    float a1 = (f1[rb + 1] + f2[col + 1] * v1) * f3[col + 1] + f4[col + 1];
                    int n = rr & 4095, b = rr >> 12;
                    int hh2 = n >> 6, ww2 = n & 63;
                    int q = ((hh2 & 1) << 1) | (ww2 & 1);
                    int p = ((hh2 >> 1) << 5) | (ww2 >> 1);
                    bf16* dst = (bf16*)Cg + ((long)(b * 4 + q) * 1024 + p) * 384 + col;
                    *(__nv_bfloat162*)dst = __floats2bfloat162_rn(a0, a1);
                } else if (ATOM) {
                    atomicAdd(&Cf[(long)rr * ldc + col], v0);
                    atomicAdd(&Cf[(long)rr * ldc + col + 1], v1);
                } else if (OUTBF) {
                    *(__nv_bfloat162*)(Cb + (long)rr * ldc + col) = __floats2bfloat162_rn(v0, v1);
                } else {
                    *(float2*)(Cf + (long)rr * ldc + col) = make_float2(v0, v1);
                }
            }
        }
    }
}

template<int EPI, int OUTBF, int ATOM>
static void bg(const bf16* A, const bf16* B, const float* bias, void* C,
               int M, int N, int K, int lda, int ldb, int ldc,
               long sA1, long sA2, long sB1, long sB2, long sC1, long sC2,
               int HB, int Z, int SK = 1,
               const float* f1 = nullptr, const float* f2 = nullptr,
               const float* f3 = nullptr, const float* f4 = nullptr)
{
    cudaFuncSetAttribute(bgemm_k<EPI, OUTBF, ATOM>,
                         cudaFuncAttributeMaxDynamicSharedMemorySize, 61440);
    dim3 grid((M + 127) / 128, (N + 127) / 128, Z * SK);
    bgemm_k<EPI, OUTBF, ATOM><<<grid, 256, 61440>>>(
        A, B, bias, C, M, N, K / SK, lda, ldb, ldc,
        sA1, sA2, sB1, sB2, sC1, sC2, HB, SK, f1, f2, f3, f4);
}

extern "C" void kernel_launch(void* const* d_in, const int* in_sizes, int n_in,
                              void* d_out, int out_size)
{
    const float* x          = (const float*)d_in[0];
    const float* convs_w    = (const float*)d_in[1];
    const float* convs_b    = (const float*)d_in[2];
    const float* pos_w      = (const float*)d_in[3];
    const float* pos_b      = (const float*)d_in[4];
    const float* ln_xca_w   = (const float*)d_in[5];
    const float* ln_xca_b   = (const float*)d_in[6];
    const float* gamma_xca  = (const float*)d_in[7];
    const float* xca_temp   = (const float*)d_in[8];
    const float* xca_kv_w   = (const float*)d_in[9];
    const float* xca_kv_b   = (const float*)d_in[10];
    const float* xca_proj_w = (const float*)d_in[11];
    const float* xca_proj_b = (const float*)d_in[12];
    const float* conv_out_w = (const float*)d_in[13];
    const float* conv_out_b = (const float*)d_in[14];
    const float* wa_kv_w    = (const float*)d_in[15];
    const float* wa_kv_b    = (const float*)d_in[16];
    const float* wa_proj_w  = (const float*)d_in[17];
    const float* wa_proj_b  = (const float*)d_in[18];
    const float* ln_w       = (const float*)d_in[19];
    const float* ln_b       = (const float*)d_in[20];
    const float* pw1_w      = (const float*)d_in[21];
    const float* pw1_b      = (const float*)d_in[22];
    const float* pw2_w      = (const float*)d_in[23];
    const float* pw2_b      = (const float*)d_in[24];
    const float* gamma      = (const float*)d_in[25];
    float* out = (float*)d_out;

    float *conv, *pos, *x3, *attn, *y, *norms;
    bf16 *bx, *lnb, *kv, *kt, *b1, *uqt, *battn, *h1, *wt;
    cudaGetSymbolAddress((void**)&conv,  g_conv);
    cudaGetSymbolAddress((void**)&pos,   g_pos);
    cudaGetSymbolAddress((void**)&x3,    g_x3);
    cudaGetSymbolAddress((void**)&attn,  g_attn);
    cudaGetSymbolAddress((void**)&y,     g_y);
    cudaGetSymbolAddress((void**)&norms, g_norms);
    cudaGetSymbolAddress((void**)&bx,    g_bx);
    cudaGetSymbolAddress((void**)&lnb,   g_lnb);
    cudaGetSymbolAddress((void**)&kv,    g_kv);
    cudaGetSymbolAddress((void**)&kt,    g_kt);
    cudaGetSymbolAddress((void**)&b1,    g_b1);
    cudaGetSymbolAddress((void**)&uqt,   g_uqt);
    cudaGetSymbolAddress((void**)&battn, g_battn);
    cudaGetSymbolAddress((void**)&h1,    g_h1);
    cudaGetSymbolAddress((void**)&wt,    g_wt);

    bf16* w_xkv   = wt;
    bf16* w_xproj = wt + 294912;
    bf16* w_wkv   = wt + 442368;
    bf16* w_wproj = wt + 737280;
    bf16* w_pw1   = wt + 884736;
    bf16* w_pw2   = wt + 1474560;

    cvtw_kernel<<<(2064384 + 255) / 256, 256>>>(xca_kv_w, xca_proj_w, wa_kv_w,
                                                wa_proj_w, pw1_w, pw2_w, wt);
    cvtx_kernel<<<(25165824 + 255) / 256, 256>>>(x, bx, uqt);

    pos_kernel<<<4096, 384>>>(pos_w, pos_b, pos);
    dwconv3_kernel<<<16 * 96, 256>>>(x, convs_w, convs_b, conv);

    dim3 tg(128, 12, 16), tb(32, 8);
    t1_kernel<<<tg, tb>>>(conv, x, pos, x3);

    // XCA
    ln_kernel<<<65536, 128>>>(x3, ln_xca_w, ln_xca_b, lnb, 0);
    bg<0,1,0>(lnb, w_xkv, xca_kv_b, kv, 65536, 768, 384, 384, 384, 768,
              0, 0, 0, 0, 0, 0, 1, 1);
    tk_kernel<<<dim3(128, 12, 16), tb>>>(kv, kt, 4096);
    norms2_k<<<768, 256>>>(kt, norms, 4096);
    zero_kernel<<<(589824 + 255) / 256, 256>>>(attn, 589824);
    bg<0,0,1>(bx, kt, nullptr, attn, 96, 96, 4096, 4096, 4096, 96,
              (long)384*4096, (long)96*4096, (long)384*4096, (long)96*4096,
              (long)4*9216, 9216, 4, 64, 4);
    xca_softmax_k<<<768, 256>>>(attn, norms, xca_temp, battn);
    bg<0,1,0>(kv + 384, battn, nullptr, b1, 4096, 96, 96, 768, 96, 384,
              (long)4096*768, 96, (long)4*9216, 9216, (long)4096*384, 96, 4, 64);
    bg<2,1,0>(b1, w_xproj, xca_proj_b, lnb, 65536, 384, 384, 384, 384, 384,
              0, 0, 0, 0, 0, 0, 1, 1, 1, x3, gamma_xca, conv_out_w, conv_out_b);

    // Window attention
    bg<0,1,0>(lnb, w_wkv, wa_kv_b, kv, 65536, 768, 384, 384, 384, 768,
              0, 0, 0, 0, 0, 0, 1, 1);
    tk_kernel<<<dim3(32, 12, 64), tb>>>(kv, kt, 1024);
    norms2_k<<<3072, 256>>>(kt, norms, 1024);
    bg<0,0,0>(uqt, kt, nullptr, attn, 96, 96, 1024, 1024, 1024, 96,
              (long)384*1024, (long)96*1024, (long)384*1024, (long)96*1024,
              (long)4*9216, 9216, 4, 256);
    wa_softmax_k<<<3072, 256>>>(attn, norms, battn);
    bf16* x2s = (bf16*)x3;
    bg<0,1,0>(battn, kv + 384, nullptr, x2s, 96, 1024, 96, 96, 768, 1024,
              (long)4*9216, 9216, (long)1024*768, 96,
              (long)96*1024, (long)64*96*1024, 4, 256);
    bg<0,0,0>(x2s, w_wproj, wa_proj_b, conv, 65536, 384, 384, 384, 384, 384,
              0, 0, 0, 0, 0, 0, 1, 1);

    // fold + LN, MLP, final residual
    ln_kernel<<<65536, 128>>>(conv, ln_w, ln_b, lnb, 1);
    bg<1,1,0>(lnb, w_pw1, pw1_b, h1, 65536, 1536, 384, 384, 384, 1536,
              0, 0, 0, 0, 0, 0, 1, 1);
    bg<0,0,0>(h1, w_pw2, pw2_b, y, 65536, 384, 1536, 1536, 1536, 384,
              0, 0, 0, 0, 0, 0, 1, 1);
    final_kernel<<<tg, tb>>>(y, x, gamma, out);
}